// round 7
// baseline (speedup 1.0000x reference)
#include <cuda_runtime.h>
#include <cuda_bf16.h>
#include <cstdint>

#define N_TYPES 8
#define D 64
#define BM 128
#define E_MAX 1048576

// ---------------- scratch ------------------------------------------------------
__device__ int g_counts[N_TYPES];
__device__ int g_cursor[N_TYPES];
__device__ int g_perm[E_MAX];
__device__ int g_is64;
// precomputed B fragments: [type][plane][ks][nt][lane] as uint2
__device__ uint2 g_bfrag[N_TYPES * 2 * 4 * 8 * 32];

// ---------------- helpers ------------------------------------------------------
__device__ __forceinline__ int get_type(const void* p, int i, int is64) {
    if (is64) return (int)((const long long*)p)[i];
    return ((const int*)p)[i];
}
__device__ __forceinline__ uint32_t bf16x2(float x0, float x1) {
    uint32_t r;
    asm("cvt.rn.bf16x2.f32 %0, %1, %2;" : "=r"(r) : "f"(x1), "f"(x0));
    return r;
}
__device__ __forceinline__ float lo_of(uint32_t w) { return __uint_as_float(w << 16); }
__device__ __forceinline__ float hi_of(uint32_t w) {
    return __uint_as_float(w & 0xffff0000u);
}
__device__ __forceinline__ void mma_bf16(float* c, const uint32_t* a,
                                         const uint32_t* b) {
    asm volatile(
        "mma.sync.aligned.m16n8k16.row.col.f32.bf16.bf16.f32 "
        "{%0,%1,%2,%3}, {%4,%5,%6,%7}, {%8,%9}, {%0,%1,%2,%3};"
        : "+f"(c[0]), "+f"(c[1]), "+f"(c[2]), "+f"(c[3])
        : "r"(a[0]), "r"(a[1]), "r"(a[2]), "r"(a[3]), "r"(b[0]), "r"(b[1]));
}
__device__ __forceinline__ void ldmx4(uint32_t* r, uint32_t addr) {
    asm volatile("ldmatrix.sync.aligned.m8n8.x4.shared.b16 {%0,%1,%2,%3}, [%4];"
                 : "=r"(r[0]), "=r"(r[1]), "=r"(r[2]), "=r"(r[3])
                 : "r"(addr));
}
__device__ __forceinline__ uint32_t smem_u32(const void* p) {
    uint32_t a;
    asm("{ .reg .u64 t; cvta.to.shared.u64 t, %1; cvt.u32.u64 %0, t; }"
        : "=r"(a) : "l"(p));
    return a;
}

// ---------------- launch 0: init + dtype detect --------------------------------
__global__ void k_init_detect(const int* __restrict__ t32, int E) {
    __shared__ int any;
    if (threadIdx.x == 0) any = 0;
    if (threadIdx.x < N_TYPES) {
        g_counts[threadIdx.x] = 0;
        g_cursor[threadIdx.x] = 0;
    }
    __syncthreads();
    int stride = E / 2048;
    if (stride < 1) stride = 1;
    for (int i = threadIdx.x; i < 1024; i += blockDim.x) {
        long long idx = 2LL * i * stride + 1;
        if (idx < E && t32[idx] != 0) any = 1;
    }
    __syncthreads();
    if (threadIdx.x == 0) g_is64 = any ? 0 : 1;
}

// ---------------- launch 1: histogram + B-fragment precompute ------------------
__global__ void k_hist(const void* __restrict__ types, const float* __restrict__ W,
                       int E) {
    __shared__ int s[N_TYPES];
    if (threadIdx.x < N_TYPES) s[threadIdx.x] = 0;
    __syncthreads();
    int is64 = g_is64;
    for (int i = blockIdx.x * blockDim.x + threadIdx.x; i < E;
         i += gridDim.x * blockDim.x) {
        atomicAdd(&s[get_type(types, i, is64)], 1);
    }
    __syncthreads();
    if (threadIdx.x < N_TYPES) atomicAdd(&g_counts[threadIdx.x], s[threadIdx.x]);

    if (blockIdx.x < N_TYPES) {
        int t = blockIdx.x;
        const float* Wt = W + (size_t)t * D * D;
        for (int it = threadIdx.x; it < 4 * 8 * 32; it += blockDim.x) {
            int ks = it >> 8;
            int nt = (it >> 5) & 7;
            int lane = it & 31;
            int col = nt * 8 + (lane >> 2);
            int k0 = ks * 16 + 2 * (lane & 3);
            float w00 = Wt[k0 * D + col];
            float w01 = Wt[(k0 + 1) * D + col];
            float w10 = Wt[(k0 + 8) * D + col];
            float w11 = Wt[(k0 + 9) * D + col];
            uint32_t b0h = bf16x2(w00, w01);
            uint32_t b1h = bf16x2(w10, w11);
            uint32_t b0l = bf16x2(w00 - lo_of(b0h), w01 - hi_of(b0h));
            uint32_t b1l = bf16x2(w10 - lo_of(b1h), w11 - hi_of(b1h));
            g_bfrag[(((t * 2 + 0) * 4 + ks) * 8 + nt) * 32 + lane] =
                make_uint2(b0h, b1h);
            g_bfrag[(((t * 2 + 1) * 4 + ks) * 8 + nt) * 32 + lane] =
                make_uint2(b0l, b1l);
        }
    }
}

// ---------------- launch 2: scatter --------------------------------------------
__global__ void k_scatter(const void* __restrict__ types, int E) {
    __shared__ int s_cnt[N_TYPES], s_base[N_TYPES];
    if (threadIdx.x < N_TYPES) s_cnt[threadIdx.x] = 0;
    __syncthreads();
    int e = blockIdx.x * blockDim.x + threadIdx.x;
    int t = 0, local = 0;
    int valid = (e < E);
    if (valid) {
        t = get_type(types, e, g_is64);
        local = atomicAdd(&s_cnt[t], 1);
    }
    __syncthreads();
    if (threadIdx.x < N_TYPES) {
        int off = 0;
        for (int u = 0; u < N_TYPES; u++) {
            if (u == threadIdx.x) break;
            off += g_counts[u];
        }
        s_base[threadIdx.x] = off + atomicAdd(&g_cursor[threadIdx.x], s_cnt[threadIdx.x]);
    }
    __syncthreads();
    if (valid) g_perm[s_base[t] + local] = e;
}

// ---------------- launch 3: ldmatrix + mma grouped GEMM ------------------------
// smem layout (dynamic, 1024-aligned):
//   [0, 32768)      A planes (hi 16KB, lo 16KB), xor-swizzled bf16
//   [32768, 49152)  B fragment image (16KB)
//   [49152, 49664)  perm cache (128 ints)
// post-MMA the [0, 36864) region is reused as fp32 staging, stride 72 floats.
static constexpr int SM_B = 32768;
static constexpr int SM_PERM = 49152;
static constexpr int SMEM_DYN = 49664 + 1024;

__global__ void __launch_bounds__(256) k_gemm_mma(const float* __restrict__ X,
                                                  const float* __restrict__ Bv,
                                                  float* __restrict__ out) {
    extern __shared__ char sm_raw[];

    // ---- map blockIdx.x -> (type, tile) ----
    int tile = blockIdx.x;
    int type = -1, row_start = 0, m = 0;
    {
        int acc_tiles = 0, off = 0;
#pragma unroll
        for (int t = 0; t < N_TYPES; t++) {
            int c = g_counts[t];
            int nt = (c + BM - 1) / BM;
            if (type < 0 && tile < acc_tiles + nt) {
                type = t;
                int lt = tile - acc_tiles;
                row_start = off + lt * BM;
                m = c - lt * BM;
                if (m > BM) m = BM;
            }
            acc_tiles += nt;
            off += c;
        }
    }
    if (type < 0) return;

    uint32_t raw = smem_u32(sm_raw);
    uint32_t base = (raw + 1023) & ~1023u;
    char* pbase = sm_raw + (base - raw);
    uint32_t sA = base;
    uint2* pB = reinterpret_cast<uint2*>(pbase + SM_B);
    int* pperm = reinterpret_cast<int*>(pbase + SM_PERM);

    int tid = threadIdx.x;
    int lane = tid & 31;
    int w = tid >> 5;

    // ---- perm cache ----
    if (tid < BM) {
        int rr = (tid < m) ? tid : (m - 1);
        pperm[tid] = g_perm[row_start + rr];
    }
    __syncthreads();

    // ---- B fragment copy: 16KB ----
    {
        const uint4* src =
            reinterpret_cast<const uint4*>(g_bfrag + (size_t)type * 2048);
        uint4* dst = reinterpret_cast<uint4*>(pB);
#pragma unroll
        for (int i = 0; i < 4; i++) dst[tid + i * 256] = src[tid + i * 256];
    }

    // ---- coalesced gather + bf16 split + swizzled STS.64 ----
    // lane: sub = lane>>4 (row within warp pair), q = lane&15 (float4 within row)
    {
        int sub = lane >> 4;
        int q = lane & 15;
        int c = q >> 1;
        int sb = (q & 1) * 8;
#pragma unroll
        for (int s = 0; s < 8; s++) {
            int r = s * 16 + w * 2 + sub;
            int e = pperm[r];
            float4 v = *reinterpret_cast<const float4*>(X + (size_t)e * D + q * 4);
            uint32_t h0 = bf16x2(v.x, v.y);
            uint32_t h1 = bf16x2(v.z, v.w);
            uint32_t l0 = bf16x2(v.x - lo_of(h0), v.y - hi_of(h0));
            uint32_t l1 = bf16x2(v.z - lo_of(h1), v.w - hi_of(h1));
            uint32_t off = (uint32_t)r * 128 + (uint32_t)((c ^ (r & 7)) << 4) + sb;
            *reinterpret_cast<uint2*>(pbase + off) = make_uint2(h0, h1);
            *reinterpret_cast<uint2*>(pbase + 16384 + off) = make_uint2(l0, l1);
        }
    }
    __syncthreads();

    // ---- main loop ----
    int wm = (w & 3) * 32;
    int wnq = (w >> 2);

    float acc[2][4][4];
#pragma unroll
    for (int mt = 0; mt < 2; mt++)
#pragma unroll
        for (int nt = 0; nt < 4; nt++)
#pragma unroll
            for (int i = 0; i < 4; i++) acc[mt][nt][i] = 0.0f;

    int lrow[2];
#pragma unroll
    for (int mt = 0; mt < 2; mt++) lrow[mt] = wm + mt * 16 + (lane & 15);
    int cadd = lane >> 4;

#pragma unroll
    for (int ks = 0; ks < 4; ks++) {
        uint32_t a[2][2][4];
#pragma unroll
        for (int mt = 0; mt < 2; mt++) {
            int c = ks * 2 + cadd;
            uint32_t off =
                (uint32_t)lrow[mt] * 128 + (uint32_t)((c ^ (lrow[mt] & 7)) << 4);
            ldmx4(a[0][mt], sA + off);
            ldmx4(a[1][mt], sA + 16384 + off);
        }
        uint32_t b[2][4][2];
#pragma unroll
        for (int p = 0; p < 2; p++)
#pragma unroll
            for (int nt = 0; nt < 4; nt++) {
                uint2 v = pB[((p * 4 + ks) * 8 + wnq * 4 + nt) * 32 + lane];
                b[p][nt][0] = v.x;
                b[p][nt][1] = v.y;
            }
#pragma unroll
        for (int mt = 0; mt < 2; mt++)
#pragma unroll
            for (int nt = 0; nt < 4; nt++) {
                mma_bf16(acc[mt][nt], a[0][mt], b[0][nt]);
                mma_bf16(acc[mt][nt], a[0][mt], b[1][nt]);
                mma_bf16(acc[mt][nt], a[1][mt], b[0][nt]);
            }
    }

    // ---- epilogue: bias + relu -> smem staging -> coalesced STG.128 ----
    int wn = wnq * 32;
    int group = lane >> 2;
    int qc = lane & 3;

    float2 bias[4];
#pragma unroll
    for (int nt = 0; nt < 4; nt++) {
        bias[nt] = *reinterpret_cast<const float2*>(Bv + (size_t)type * D + wn +
                                                    nt * 8 + qc * 2);
    }

    __syncthreads();  // A/B smem dead; reuse as staging (stride 72 floats)
    float* stg = reinterpret_cast<float*>(pbase);
#pragma unroll
    for (int mt = 0; mt < 2; mt++) {
#pragma unroll
        for (int half = 0; half < 2; half++) {
            int r = wm + mt * 16 + group + half * 8;
#pragma unroll
            for (int nt = 0; nt < 4; nt++) {
                float v0 = fmaxf(acc[mt][nt][half * 2 + 0] + bias[nt].x, 0.0f);
                float v1 = fmaxf(acc[mt][nt][half * 2 + 1] + bias[nt].y, 0.0f);
                *reinterpret_cast<float2*>(stg + r * 72 + wn + nt * 8 + qc * 2) =
                    make_float2(v0, v1);
            }
        }
    }
    __syncthreads();

    {
        int sub = lane >> 4;
        int q = lane & 15;
#pragma unroll
        for (int s = 0; s < 8; s++) {
            int r = s * 16 + w * 2 + sub;
            if (r < m) {
                int e = pperm[r];
                float4 v = *reinterpret_cast<const float4*>(stg + r * 72 + q * 4);
                *reinterpret_cast<float4*>(out + (size_t)e * D + q * 4) = v;
            }
        }
    }
}

// ---------------- launch -------------------------------------------------------
extern "C" void kernel_launch(void* const* d_in, const int* in_sizes, int n_in,
                              void* d_out, int out_size) {
    const float* X = (const float*)d_in[0];
    const void* types = d_in[1];
    const float* W = (const float*)d_in[2];
    const float* Bv = (const float*)d_in[3];
    float* out = (float*)d_out;
    int E = in_sizes[0] / D;

    cudaFuncSetAttribute(k_gemm_mma, cudaFuncAttributeMaxDynamicSharedMemorySize,
                         SMEM_DYN);

    k_init_detect<<<1, 256>>>((const int*)types, E);
    k_hist<<<512, 256>>>(types, W, E);
    k_scatter<<<(E + 255) / 256, 256>>>(types, E);

    int max_tiles = (E + BM - 1) / BM + N_TYPES;
    k_gemm_mma<<<max_tiles, 256, SMEM_DYN>>>(X, Bv, out);
}

// round 8
// speedup vs baseline: 1.2841x; 1.2841x over previous
#include <cuda_runtime.h>
#include <cuda_bf16.h>
#include <cstdint>

#define N_TYPES 8
#define D 64
#define BM 128
#define E_MAX 1048576

// ---------------- scratch ------------------------------------------------------
__device__ int g_counts[N_TYPES];
__device__ int g_cursor[N_TYPES];
__device__ int g_perm[E_MAX];
__device__ int g_is64;
// precomputed B fragments: [type][plane][ks][nt][lane] as uint2
__device__ uint2 g_bfrag[N_TYPES * 2 * 4 * 8 * 32];

// ---------------- helpers ------------------------------------------------------
__device__ __forceinline__ int get_type(const void* p, int i, int is64) {
    if (is64) return (int)((const long long*)p)[i];
    return ((const int*)p)[i];
}
__device__ __forceinline__ uint32_t bf16x2(float x0, float x1) {
    uint32_t r;
    asm("cvt.rn.bf16x2.f32 %0, %1, %2;" : "=r"(r) : "f"(x1), "f"(x0));
    return r;
}
__device__ __forceinline__ float lo_of(uint32_t w) { return __uint_as_float(w << 16); }
__device__ __forceinline__ float hi_of(uint32_t w) {
    return __uint_as_float(w & 0xffff0000u);
}
__device__ __forceinline__ void mma_bf16(float* c, const uint32_t* a,
                                         const uint32_t* b) {
    asm volatile(
        "mma.sync.aligned.m16n8k16.row.col.f32.bf16.bf16.f32 "
        "{%0,%1,%2,%3}, {%4,%5,%6,%7}, {%8,%9}, {%0,%1,%2,%3};"
        : "+f"(c[0]), "+f"(c[1]), "+f"(c[2]), "+f"(c[3])
        : "r"(a[0]), "r"(a[1]), "r"(a[2]), "r"(a[3]), "r"(b[0]), "r"(b[1]));
}
__device__ __forceinline__ void ldmx4(uint32_t* r, uint32_t addr) {
    asm volatile("ldmatrix.sync.aligned.m8n8.x4.shared.b16 {%0,%1,%2,%3}, [%4];"
                 : "=r"(r[0]), "=r"(r[1]), "=r"(r[2]), "=r"(r[3])
                 : "r"(addr));
}
__device__ __forceinline__ uint32_t smem_u32(const void* p) {
    uint32_t a;
    asm("{ .reg .u64 t; cvta.to.shared.u64 t, %1; cvt.u32.u64 %0, t; }"
        : "=r"(a) : "l"(p));
    return a;
}

// ---------------- launch 0: init + dtype detect --------------------------------
__global__ void k_init_detect(const int* __restrict__ t32, int E) {
    __shared__ int any;
    if (threadIdx.x == 0) any = 0;
    if (threadIdx.x < N_TYPES) {
        g_counts[threadIdx.x] = 0;
        g_cursor[threadIdx.x] = 0;
    }
    __syncthreads();
    int stride = E / 2048;
    if (stride < 1) stride = 1;
    for (int i = threadIdx.x; i < 1024; i += blockDim.x) {
        long long idx = 2LL * i * stride + 1;
        if (idx < E && t32[idx] != 0) any = 1;
    }
    __syncthreads();
    if (threadIdx.x == 0) g_is64 = any ? 0 : 1;
}

// ---------------- launch 1: histogram + B-fragment precompute ------------------
__global__ void k_hist(const void* __restrict__ types, const float* __restrict__ W,
                       int E) {
    __shared__ int s[N_TYPES];
    if (threadIdx.x < N_TYPES) s[threadIdx.x] = 0;
    __syncthreads();
    int is64 = g_is64;
    for (int i = blockIdx.x * blockDim.x + threadIdx.x; i < E;
         i += gridDim.x * blockDim.x) {
        atomicAdd(&s[get_type(types, i, is64)], 1);
    }
    __syncthreads();
    if (threadIdx.x < N_TYPES) atomicAdd(&g_counts[threadIdx.x], s[threadIdx.x]);

    if (blockIdx.x < N_TYPES) {
        int t = blockIdx.x;
        const float* Wt = W + (size_t)t * D * D;
        for (int it = threadIdx.x; it < 4 * 8 * 32; it += blockDim.x) {
            int ks = it >> 8;
            int nt = (it >> 5) & 7;
            int lane = it & 31;
            int col = nt * 8 + (lane >> 2);
            int k0 = ks * 16 + 2 * (lane & 3);
            float w00 = Wt[k0 * D + col];
            float w01 = Wt[(k0 + 1) * D + col];
            float w10 = Wt[(k0 + 8) * D + col];
            float w11 = Wt[(k0 + 9) * D + col];
            uint32_t b0h = bf16x2(w00, w01);
            uint32_t b1h = bf16x2(w10, w11);
            uint32_t b0l = bf16x2(w00 - lo_of(b0h), w01 - hi_of(b0h));
            uint32_t b1l = bf16x2(w10 - lo_of(b1h), w11 - hi_of(b1h));
            g_bfrag[(((t * 2 + 0) * 4 + ks) * 8 + nt) * 32 + lane] =
                make_uint2(b0h, b1h);
            g_bfrag[(((t * 2 + 1) * 4 + ks) * 8 + nt) * 32 + lane] =
                make_uint2(b0l, b1l);
        }
    }
}

// ---------------- launch 2: scatter --------------------------------------------
__global__ void k_scatter(const void* __restrict__ types, int E) {
    __shared__ int s_cnt[N_TYPES], s_base[N_TYPES];
    if (threadIdx.x < N_TYPES) s_cnt[threadIdx.x] = 0;
    __syncthreads();
    int e = blockIdx.x * blockDim.x + threadIdx.x;
    int t = 0, local = 0;
    int valid = (e < E);
    if (valid) {
        t = get_type(types, e, g_is64);
        local = atomicAdd(&s_cnt[t], 1);
    }
    __syncthreads();
    if (threadIdx.x < N_TYPES) {
        int off = 0;
        for (int u = 0; u < N_TYPES; u++) {
            if (u == threadIdx.x) break;
            off += g_counts[u];
        }
        s_base[threadIdx.x] = off + atomicAdd(&g_cursor[threadIdx.x], s_cnt[threadIdx.x]);
    }
    __syncthreads();
    if (valid) g_perm[s_base[t] + local] = e;
}

// ---------------- launch 3: ldmatrix + mma grouped GEMM ------------------------
// smem (dynamic, 1024-aligned): A planes 32KB | B frags 16KB | perm 512B
// Coalesced gather (R7), direct scattered epilogue (R6), single mid syncthreads.
static constexpr int SM_B = 32768;
static constexpr int SM_PERM = 49152;
static constexpr int SMEM_DYN = 49664 + 1024;

__global__ void __launch_bounds__(256, 3) k_gemm_mma(const float* __restrict__ X,
                                                     const float* __restrict__ Bv,
                                                     float* __restrict__ out) {
    extern __shared__ char sm_raw[];

    // ---- map blockIdx.x -> (type, tile) ----
    int tile = blockIdx.x;
    int type = -1, row_start = 0, m = 0;
    {
        int acc_tiles = 0, off = 0;
#pragma unroll
        for (int t = 0; t < N_TYPES; t++) {
            int c = g_counts[t];
            int nt = (c + BM - 1) / BM;
            if (type < 0 && tile < acc_tiles + nt) {
                type = t;
                int lt = tile - acc_tiles;
                row_start = off + lt * BM;
                m = c - lt * BM;
                if (m > BM) m = BM;
            }
            acc_tiles += nt;
            off += c;
        }
    }
    if (type < 0) return;

    uint32_t raw = smem_u32(sm_raw);
    uint32_t base = (raw + 1023) & ~1023u;
    char* pbase = sm_raw + (base - raw);
    uint32_t sA = base;
    uint2* pB = reinterpret_cast<uint2*>(pbase + SM_B);
    int* pperm = reinterpret_cast<int*>(pbase + SM_PERM);

    int tid = threadIdx.x;
    int lane = tid & 31;
    int w = tid >> 5;

    // ---- perm cache (coalesced LDG, reused by gather + epilogue) ----
    if (tid < BM) {
        int rr = (tid < m) ? tid : (m - 1);
        pperm[tid] = g_perm[row_start + rr];
    }

    // ---- B fragment copy: 16KB ----
    {
        const uint4* src =
            reinterpret_cast<const uint4*>(g_bfrag + (size_t)type * 2048);
        uint4* dst = reinterpret_cast<uint4*>(pB);
#pragma unroll
        for (int i = 0; i < 4; i++) dst[tid + i * 256] = src[tid + i * 256];
    }
    __syncthreads();  // pperm ready for gather

    // ---- coalesced gather + bf16 split + swizzled STS.64 ----
    {
        int sub = lane >> 4;
        int q = lane & 15;
        int c = q >> 1;
        int sb = (q & 1) * 8;
#pragma unroll
        for (int s = 0; s < 8; s++) {
            int r = s * 16 + w * 2 + sub;
            int e = pperm[r];
            float4 v = *reinterpret_cast<const float4*>(X + (size_t)e * D + q * 4);
            uint32_t h0 = bf16x2(v.x, v.y);
            uint32_t h1 = bf16x2(v.z, v.w);
            uint32_t l0 = bf16x2(v.x - lo_of(h0), v.y - hi_of(h0));
            uint32_t l1 = bf16x2(v.z - lo_of(h1), v.w - hi_of(h1));
            uint32_t off = (uint32_t)r * 128 + (uint32_t)((c ^ (r & 7)) << 4) + sb;
            *reinterpret_cast<uint2*>(pbase + off) = make_uint2(h0, h1);
            *reinterpret_cast<uint2*>(pbase + 16384 + off) = make_uint2(l0, l1);
        }
    }
    __syncthreads();

    // ---- main loop ----
    int wm = (w & 3) * 32;
    int wnq = (w >> 2);

    float acc[2][4][4];
#pragma unroll
    for (int mt = 0; mt < 2; mt++)
#pragma unroll
        for (int nt = 0; nt < 4; nt++)
#pragma unroll
            for (int i = 0; i < 4; i++) acc[mt][nt][i] = 0.0f;

    int lrow[2];
#pragma unroll
    for (int mt = 0; mt < 2; mt++) lrow[mt] = wm + mt * 16 + (lane & 15);
    int cadd = lane >> 4;

#pragma unroll
    for (int ks = 0; ks < 4; ks++) {
        uint32_t a[2][2][4];
#pragma unroll
        for (int mt = 0; mt < 2; mt++) {
            int c = ks * 2 + cadd;
            uint32_t off =
                (uint32_t)lrow[mt] * 128 + (uint32_t)((c ^ (lrow[mt] & 7)) << 4);
            ldmx4(a[0][mt], sA + off);
            ldmx4(a[1][mt], sA + 16384 + off);
        }
        uint32_t b[2][4][2];
#pragma unroll
        for (int p = 0; p < 2; p++)
#pragma unroll
            for (int nt = 0; nt < 4; nt++) {
                uint2 v = pB[((p * 4 + ks) * 8 + wnq * 4 + nt) * 32 + lane];
                b[p][nt][0] = v.x;
                b[p][nt][1] = v.y;
            }
#pragma unroll
        for (int mt = 0; mt < 2; mt++)
#pragma unroll
            for (int nt = 0; nt < 4; nt++) {
                mma_bf16(acc[mt][nt], a[0][mt], b[0][nt]);
                mma_bf16(acc[mt][nt], a[0][mt], b[1][nt]);
                mma_bf16(acc[mt][nt], a[1][mt], b[0][nt]);
            }
    }

    // ---- epilogue: bias + relu + direct scattered store (no staging) ----
    int wn = wnq * 32;
    int group = lane >> 2;
    int qc = lane & 3;

    float2 bias[4];
#pragma unroll
    for (int nt = 0; nt < 4; nt++) {
        bias[nt] = *reinterpret_cast<const float2*>(Bv + (size_t)type * D + wn +
                                                    nt * 8 + qc * 2);
    }

#pragma unroll
    for (int mt = 0; mt < 2; mt++) {
#pragma unroll
        for (int half = 0; half < 2; half++) {
            int r = wm + mt * 16 + group + half * 8;
            if (r < m) {
                int e = pperm[r];
                float* orow = out + (size_t)e * D;
#pragma unroll
                for (int nt = 0; nt < 4; nt++) {
                    float v0 = fmaxf(acc[mt][nt][half * 2 + 0] + bias[nt].x, 0.0f);
                    float v1 = fmaxf(acc[mt][nt][half * 2 + 1] + bias[nt].y, 0.0f);
                    *reinterpret_cast<float2*>(orow + wn + nt * 8 + qc * 2) =
                        make_float2(v0, v1);
                }
            }
        }
    }
}

// ---------------- launch -------------------------------------------------------
extern "C" void kernel_launch(void* const* d_in, const int* in_sizes, int n_in,
                              void* d_out, int out_size) {
    const float* X = (const float*)d_in[0];
    const void* types = d_in[1];
    const float* W = (const float*)d_in[2];
    const float* Bv = (const float*)d_in[3];
    float* out = (float*)d_out;
    int E = in_sizes[0] / D;

    cudaFuncSetAttribute(k_gemm_mma, cudaFuncAttributeMaxDynamicSharedMemorySize,
                         SMEM_DYN);
    cudaFuncSetAttribute(k_gemm_mma,
                         cudaFuncAttributePreferredSharedMemoryCarveout, 100);

    k_init_detect<<<1, 256>>>((const int*)types, E);
    k_hist<<<512, 256>>>(types, W, E);
    k_scatter<<<(E + 255) / 256, 256>>>(types, E);

    int max_tiles = (E + BM - 1) / BM + N_TYPES;
    k_gemm_mma<<<max_tiles, 256, SMEM_DYN>>>(X, Bv, out);
}

// round 9
// speedup vs baseline: 1.5886x; 1.2372x over previous
#include <cuda_runtime.h>
#include <cuda_bf16.h>
#include <cstdint>

#define N_TYPES 8
#define D 64
#define BM 128
#define E_MAX 1048576

// ---------------- scratch ------------------------------------------------------
__device__ int g_counts[N_TYPES];
__device__ int g_cursor[N_TYPES];
__device__ int g_perm[E_MAX];
__device__ int g_is64;
// precomputed B fragments: [type][plane][ks][nt][lane] as uint2
__device__ uint2 g_bfrag[N_TYPES * 2 * 4 * 8 * 32];

// ---------------- helpers ------------------------------------------------------
__device__ __forceinline__ int get_type(const void* p, int i, int is64) {
    if (is64) return (int)((const long long*)p)[i];
    return ((const int*)p)[i];
}
__device__ __forceinline__ uint32_t bf16x2(float x0, float x1) {
    uint32_t r;
    asm("cvt.rn.bf16x2.f32 %0, %1, %2;" : "=r"(r) : "f"(x1), "f"(x0));
    return r;
}
__device__ __forceinline__ float lo_of(uint32_t w) { return __uint_as_float(w << 16); }
__device__ __forceinline__ float hi_of(uint32_t w) {
    return __uint_as_float(w & 0xffff0000u);
}
__device__ __forceinline__ void mma_bf16(float* c, const uint32_t* a,
                                         const uint32_t* b) {
    asm volatile(
        "mma.sync.aligned.m16n8k16.row.col.f32.bf16.bf16.f32 "
        "{%0,%1,%2,%3}, {%4,%5,%6,%7}, {%8,%9}, {%0,%1,%2,%3};"
        : "+f"(c[0]), "+f"(c[1]), "+f"(c[2]), "+f"(c[3])
        : "r"(a[0]), "r"(a[1]), "r"(a[2]), "r"(a[3]), "r"(b[0]), "r"(b[1]));
}
__device__ __forceinline__ void ldmx4(uint32_t* r, uint32_t addr) {
    asm volatile("ldmatrix.sync.aligned.m8n8.x4.shared.b16 {%0,%1,%2,%3}, [%4];"
                 : "=r"(r[0]), "=r"(r[1]), "=r"(r[2]), "=r"(r[3])
                 : "r"(addr));
}
__device__ __forceinline__ uint32_t smem_u32(const void* p) {
    uint32_t a;
    asm("{ .reg .u64 t; cvta.to.shared.u64 t, %1; cvt.u32.u64 %0, t; }"
        : "=r"(a) : "l"(p));
    return a;
}

// ---------------- launch 0: init + dtype detect --------------------------------
__global__ void k_init_detect(const int* __restrict__ t32, int E) {
    __shared__ int any;
    if (threadIdx.x == 0) any = 0;
    if (threadIdx.x < N_TYPES) {
        g_counts[threadIdx.x] = 0;
        g_cursor[threadIdx.x] = 0;
    }
    __syncthreads();
    int stride = E / 2048;
    if (stride < 1) stride = 1;
    for (int i = threadIdx.x; i < 1024; i += blockDim.x) {
        long long idx = 2LL * i * stride + 1;
        if (idx < E && t32[idx] != 0) any = 1;
    }
    __syncthreads();
    if (threadIdx.x == 0) g_is64 = any ? 0 : 1;
}

// ---------------- launch 1: histogram + B-fragment precompute ------------------
__global__ void k_hist(const void* __restrict__ types, const float* __restrict__ W,
                       int E) {
    __shared__ int s[N_TYPES];
    if (threadIdx.x < N_TYPES) s[threadIdx.x] = 0;
    __syncthreads();
    int is64 = g_is64;
    for (int i = blockIdx.x * blockDim.x + threadIdx.x; i < E;
         i += gridDim.x * blockDim.x) {
        atomicAdd(&s[get_type(types, i, is64)], 1);
    }
    __syncthreads();
    if (threadIdx.x < N_TYPES) atomicAdd(&g_counts[threadIdx.x], s[threadIdx.x]);

    if (blockIdx.x < N_TYPES) {
        int t = blockIdx.x;
        const float* Wt = W + (size_t)t * D * D;
        for (int it = threadIdx.x; it < 4 * 8 * 32; it += blockDim.x) {
            int ks = it >> 8;
            int nt = (it >> 5) & 7;
            int lane = it & 31;
            int col = nt * 8 + (lane >> 2);
            int k0 = ks * 16 + 2 * (lane & 3);
            float w00 = Wt[k0 * D + col];
            float w01 = Wt[(k0 + 1) * D + col];
            float w10 = Wt[(k0 + 8) * D + col];
            float w11 = Wt[(k0 + 9) * D + col];
            uint32_t b0h = bf16x2(w00, w01);
            uint32_t b1h = bf16x2(w10, w11);
            uint32_t b0l = bf16x2(w00 - lo_of(b0h), w01 - hi_of(b0h));
            uint32_t b1l = bf16x2(w10 - lo_of(b1h), w11 - hi_of(b1h));
            g_bfrag[(((t * 2 + 0) * 4 + ks) * 8 + nt) * 32 + lane] =
                make_uint2(b0h, b1h);
            g_bfrag[(((t * 2 + 1) * 4 + ks) * 8 + nt) * 32 + lane] =
                make_uint2(b0l, b1l);
        }
    }
}

// ---------------- launch 2: scatter --------------------------------------------
__global__ void k_scatter(const void* __restrict__ types, int E) {
    __shared__ int s_cnt[N_TYPES], s_base[N_TYPES];
    if (threadIdx.x < N_TYPES) s_cnt[threadIdx.x] = 0;
    __syncthreads();
    int e = blockIdx.x * blockDim.x + threadIdx.x;
    int t = 0, local = 0;
    int valid = (e < E);
    if (valid) {
        t = get_type(types, e, g_is64);
        local = atomicAdd(&s_cnt[t], 1);
    }
    __syncthreads();
    if (threadIdx.x < N_TYPES) {
        int off = 0;
        for (int u = 0; u < N_TYPES; u++) {
            if (u == threadIdx.x) break;
            off += g_counts[u];
        }
        s_base[threadIdx.x] = off + atomicAdd(&g_cursor[threadIdx.x], s_cnt[threadIdx.x]);
    }
    __syncthreads();
    if (valid) g_perm[s_base[t] + local] = e;
}

// ---------------- launch 3: persistent pipelined grouped GEMM ------------------
// smem: A planes 32KB | B frags 16KB | perm double buffer 2x512B
static constexpr int SM_B = 32768;
static constexpr int SM_PERM = 49152;  // [2][128] ints
static constexpr int SMEM_DYN = 50176 + 1024;
static constexpr int NCTA = 304;

struct TileInfo {
    int type, row_start, m;
};

__device__ __forceinline__ TileInfo map_tile(int tl) {
    TileInfo ti;
    ti.type = -1;
    ti.row_start = 0;
    ti.m = 0;
    int acc_tiles = 0, off = 0;
#pragma unroll
    for (int t = 0; t < N_TYPES; t++) {
        int c = g_counts[t];
        int nt = (c + BM - 1) / BM;
        if (ti.type < 0 && tl < acc_tiles + nt) {
            ti.type = t;
            int lt = tl - acc_tiles;
            ti.row_start = off + lt * BM;
            ti.m = c - lt * BM;
            if (ti.m > BM) ti.m = BM;
        }
        acc_tiles += nt;
        off += c;
    }
    return ti;
}

__global__ void __launch_bounds__(256, 2) k_gemm_mma(const float* __restrict__ X,
                                                     const float* __restrict__ Bv,
                                                     float* __restrict__ out) {
    extern __shared__ char sm_raw[];
    uint32_t raw = smem_u32(sm_raw);
    uint32_t base = (raw + 1023) & ~1023u;
    char* pbase = sm_raw + (base - raw);
    uint32_t sA = base;
    uint2* pB = reinterpret_cast<uint2*>(pbase + SM_B);
    int* pperm = reinterpret_cast<int*>(pbase + SM_PERM);  // [2][128]

    int tid = threadIdx.x;
    int lane = tid & 31;
    int w = tid >> 5;

    // total tiles
    int ntiles = 0;
#pragma unroll
    for (int t = 0; t < N_TYPES; t++) ntiles += (g_counts[t] + BM - 1) / BM;

    // lane maps (fixed)
    int sub = lane >> 4;        // gather: row-within-pair
    int q = lane & 15;          // gather: float4 within row
    int gc = q >> 1;            // gather: 16B chunk
    int gsb = (q & 1) * 8;      // gather: 8B sub-offset
    int wm = (w & 3) * 32;      // mma warp m offset
    int wnq = (w >> 2);         // mma warp n quadrant
    int wn = wnq * 32;
    int group = lane >> 2;
    int qc = lane & 3;
    int lrow[2];
#pragma unroll
    for (int mt = 0; mt < 2; mt++) lrow[mt] = wm + mt * 16 + (lane & 15);
    int cadd = lane >> 4;

    int tl = blockIdx.x;
    if (tl >= ntiles) return;

    // ---- prologue: perm + X for first tile ----
    TileInfo cur = map_tile(tl);
    if (tid < BM) {
        int rr = (tid < cur.m) ? tid : (cur.m - 1);
        pperm[tid] = g_perm[cur.row_start + rr];
    }
    __syncthreads();
    float4 xreg[8];
    {
        const int* pp = pperm;
#pragma unroll
        for (int s = 0; s < 8; s++) {
            int r = s * 16 + w * 2 + sub;
            int e = pp[r];
            xreg[s] = *reinterpret_cast<const float4*>(X + (size_t)e * D + q * 4);
        }
    }

    int buf = 0;
    int btype = -1;

    for (; tl < ntiles; tl += NCTA) {
        // ---- B fragments (only when type changes) ----
        if (cur.type != btype) {
            const uint4* src =
                reinterpret_cast<const uint4*>(g_bfrag + (size_t)cur.type * 2048);
            uint4* dst = reinterpret_cast<uint4*>(pB);
#pragma unroll
            for (int i = 0; i < 4; i++) dst[tid + i * 256] = src[tid + i * 256];
            btype = cur.type;
        }

        // ---- convert current X regs -> bf16 planes in smem A ----
#pragma unroll
        for (int s = 0; s < 8; s++) {
            int r = s * 16 + w * 2 + sub;
            float4 v = xreg[s];
            uint32_t h0 = bf16x2(v.x, v.y);
            uint32_t h1 = bf16x2(v.z, v.w);
            uint32_t l0 = bf16x2(v.x - lo_of(h0), v.y - hi_of(h0));
            uint32_t l1 = bf16x2(v.z - lo_of(h1), v.w - hi_of(h1));
            uint32_t off = (uint32_t)r * 128 + (uint32_t)((gc ^ (r & 7)) << 4) + gsb;
            *reinterpret_cast<uint2*>(pbase + off) = make_uint2(h0, h1);
            *reinterpret_cast<uint2*>(pbase + 16384 + off) = make_uint2(l0, l1);
        }

        // ---- prefetch next tile's perm ----
        int tln = tl + NCTA;
        bool hasnext = (tln < ntiles);
        TileInfo nxt;
        if (hasnext) {
            nxt = map_tile(tln);
            if (tid < BM) {
                int rr = (tid < nxt.m) ? tid : (nxt.m - 1);
                pperm[(buf ^ 1) * BM + tid] = g_perm[nxt.row_start + rr];
            }
        }
        __syncthreads();  // A + perm_next visible

        // ---- prefetch next tile's X into regs (overlaps MMA below) ----
        if (hasnext) {
            const int* pp = pperm + (buf ^ 1) * BM;
#pragma unroll
            for (int s = 0; s < 8; s++) {
                int r = s * 16 + w * 2 + sub;
                int e = pp[r];
                xreg[s] =
                    *reinterpret_cast<const float4*>(X + (size_t)e * D + q * 4);
            }
        }

        // ---- MMA ----
        float acc[2][4][4];
#pragma unroll
        for (int mt = 0; mt < 2; mt++)
#pragma unroll
            for (int nt = 0; nt < 4; nt++)
#pragma unroll
                for (int i = 0; i < 4; i++) acc[mt][nt][i] = 0.0f;

#pragma unroll
        for (int ks = 0; ks < 4; ks++) {
            uint32_t a[2][2][4];
#pragma unroll
            for (int mt = 0; mt < 2; mt++) {
                int c = ks * 2 + cadd;
                uint32_t off =
                    (uint32_t)lrow[mt] * 128 + (uint32_t)((c ^ (lrow[mt] & 7)) << 4);
                ldmx4(a[0][mt], sA + off);
                ldmx4(a[1][mt], sA + 16384 + off);
            }
            uint32_t b[2][4][2];
#pragma unroll
            for (int p = 0; p < 2; p++)
#pragma unroll
                for (int nt = 0; nt < 4; nt++) {
                    uint2 v = pB[((p * 4 + ks) * 8 + wnq * 4 + nt) * 32 + lane];
                    b[p][nt][0] = v.x;
                    b[p][nt][1] = v.y;
                }
#pragma unroll
            for (int mt = 0; mt < 2; mt++)
#pragma unroll
                for (int nt = 0; nt < 4; nt++) {
                    mma_bf16(acc[mt][nt], a[0][mt], b[0][nt]);
                    mma_bf16(acc[mt][nt], a[0][mt], b[1][nt]);
                    mma_bf16(acc[mt][nt], a[1][mt], b[0][nt]);
                }
        }

        // ---- epilogue: bias + relu + scattered store ----
        float2 bias[4];
#pragma unroll
        for (int nt = 0; nt < 4; nt++) {
            bias[nt] = *reinterpret_cast<const float2*>(Bv + (size_t)cur.type * D +
                                                        wn + nt * 8 + qc * 2);
        }
        const int* ppc = pperm + buf * BM;
#pragma unroll
        for (int mt = 0; mt < 2; mt++) {
#pragma unroll
            for (int half = 0; half < 2; half++) {
                int r = wm + mt * 16 + group + half * 8;
                if (r < cur.m) {
                    int e = ppc[r];
                    float* orow = out + (size_t)e * D;
#pragma unroll
                    for (int nt = 0; nt < 4; nt++) {
                        float v0 = fmaxf(acc[mt][nt][half * 2 + 0] + bias[nt].x, 0.0f);
                        float v1 = fmaxf(acc[mt][nt][half * 2 + 1] + bias[nt].y, 0.0f);
                        *reinterpret_cast<float2*>(orow + wn + nt * 8 + qc * 2) =
                            make_float2(v0, v1);
                    }
                }
            }
        }

        __syncthreads();  // A smem fully consumed before next overwrite
        cur = nxt;
        buf ^= 1;
    }
}

// ---------------- launch -------------------------------------------------------
extern "C" void kernel_launch(void* const* d_in, const int* in_sizes, int n_in,
                              void* d_out, int out_size) {
    const float* X = (const float*)d_in[0];
    const void* types = d_in[1];
    const float* W = (const float*)d_in[2];
    const float* Bv = (const float*)d_in[3];
    float* out = (float*)d_out;
    int E = in_sizes[0] / D;

    cudaFuncSetAttribute(k_gemm_mma, cudaFuncAttributeMaxDynamicSharedMemorySize,
                         SMEM_DYN);
    cudaFuncSetAttribute(k_gemm_mma,
                         cudaFuncAttributePreferredSharedMemoryCarveout, 100);

    k_init_detect<<<1, 256>>>((const int*)types, E);
    k_hist<<<512, 256>>>(types, W, E);
    k_scatter<<<(E + 255) / 256, 256>>>(types, E);

    k_gemm_mma<<<NCTA, 256, SMEM_DYN>>>(X, Bv, out);
}

// round 10
// speedup vs baseline: 1.6778x; 1.0561x over previous
#include <cuda_runtime.h>
#include <cuda_bf16.h>
#include <cstdint>

#define N_TYPES 8
#define D 64
#define BM 128
#define E_MAX 1048576

// ---------------- scratch ------------------------------------------------------
__device__ int g_counts[N_TYPES];
__device__ int g_cursor[N_TYPES];
__device__ int g_perm[E_MAX];
__device__ int g_is64;
// precomputed B fragments: [type][plane][ks][nt][lane] as uint2
__device__ uint2 g_bfrag[N_TYPES * 2 * 4 * 8 * 32];

// ---------------- helpers ------------------------------------------------------
__device__ __forceinline__ int get_type(const void* p, int i, int is64) {
    if (is64) return (int)((const long long*)p)[i];
    return ((const int*)p)[i];
}
__device__ __forceinline__ uint32_t bf16x2(float x0, float x1) {
    uint32_t r;
    asm("cvt.rn.bf16x2.f32 %0, %1, %2;" : "=r"(r) : "f"(x1), "f"(x0));
    return r;
}
__device__ __forceinline__ float lo_of(uint32_t w) { return __uint_as_float(w << 16); }
__device__ __forceinline__ float hi_of(uint32_t w) {
    return __uint_as_float(w & 0xffff0000u);
}
__device__ __forceinline__ void mma_bf16(float* c, const uint32_t* a,
                                         const uint32_t* b) {
    asm volatile(
        "mma.sync.aligned.m16n8k16.row.col.f32.bf16.bf16.f32 "
        "{%0,%1,%2,%3}, {%4,%5,%6,%7}, {%8,%9}, {%0,%1,%2,%3};"
        : "+f"(c[0]), "+f"(c[1]), "+f"(c[2]), "+f"(c[3])
        : "r"(a[0]), "r"(a[1]), "r"(a[2]), "r"(a[3]), "r"(b[0]), "r"(b[1]));
}
__device__ __forceinline__ void ldmx4(uint32_t* r, uint32_t addr) {
    asm volatile("ldmatrix.sync.aligned.m8n8.x4.shared.b16 {%0,%1,%2,%3}, [%4];"
                 : "=r"(r[0]), "=r"(r[1]), "=r"(r[2]), "=r"(r[3])
                 : "r"(addr));
}
__device__ __forceinline__ uint32_t smem_u32(const void* p) {
    uint32_t a;
    asm("{ .reg .u64 t; cvta.to.shared.u64 t, %1; cvt.u32.u64 %0, t; }"
        : "=r"(a) : "l"(p));
    return a;
}
__device__ __forceinline__ void cp_async16(uint32_t dst, const void* src) {
    asm volatile("cp.async.cg.shared.global [%0], [%1], 16;" ::"r"(dst), "l"(src)
                 : "memory");
}
__device__ __forceinline__ void cp_commit() {
    asm volatile("cp.async.commit_group;" ::: "memory");
}
__device__ __forceinline__ void cp_wait0() {
    asm volatile("cp.async.wait_group 0;" ::: "memory");
}

// ---------------- launch 0: init + dtype detect --------------------------------
__global__ void k_init_detect(const int* __restrict__ t32, int E) {
    __shared__ int any;
    if (threadIdx.x == 0) any = 0;
    if (threadIdx.x < N_TYPES) {
        g_counts[threadIdx.x] = 0;
        g_cursor[threadIdx.x] = 0;
    }
    __syncthreads();
    int stride = E / 2048;
    if (stride < 1) stride = 1;
    for (int i = threadIdx.x; i < 1024; i += blockDim.x) {
        long long idx = 2LL * i * stride + 1;
        if (idx < E && t32[idx] != 0) any = 1;
    }
    __syncthreads();
    if (threadIdx.x == 0) g_is64 = any ? 0 : 1;
}

// ---------------- launch 1: histogram + B-fragment precompute ------------------
__global__ void k_hist(const void* __restrict__ types, const float* __restrict__ W,
                       int E) {
    __shared__ int s[N_TYPES];
    if (threadIdx.x < N_TYPES) s[threadIdx.x] = 0;
    __syncthreads();
    int is64 = g_is64;
    for (int i = blockIdx.x * blockDim.x + threadIdx.x; i < E;
         i += gridDim.x * blockDim.x) {
        atomicAdd(&s[get_type(types, i, is64)], 1);
    }
    __syncthreads();
    if (threadIdx.x < N_TYPES) atomicAdd(&g_counts[threadIdx.x], s[threadIdx.x]);

    if (blockIdx.x < N_TYPES) {
        int t = blockIdx.x;
        const float* Wt = W + (size_t)t * D * D;
        for (int it = threadIdx.x; it < 4 * 8 * 32; it += blockDim.x) {
            int ks = it >> 8;
            int nt = (it >> 5) & 7;
            int lane = it & 31;
            int col = nt * 8 + (lane >> 2);
            int k0 = ks * 16 + 2 * (lane & 3);
            float w00 = Wt[k0 * D + col];
            float w01 = Wt[(k0 + 1) * D + col];
            float w10 = Wt[(k0 + 8) * D + col];
            float w11 = Wt[(k0 + 9) * D + col];
            uint32_t b0h = bf16x2(w00, w01);
            uint32_t b1h = bf16x2(w10, w11);
            uint32_t b0l = bf16x2(w00 - lo_of(b0h), w01 - hi_of(b0h));
            uint32_t b1l = bf16x2(w10 - lo_of(b1h), w11 - hi_of(b1h));
            g_bfrag[(((t * 2 + 0) * 4 + ks) * 8 + nt) * 32 + lane] =
                make_uint2(b0h, b1h);
            g_bfrag[(((t * 2 + 1) * 4 + ks) * 8 + nt) * 32 + lane] =
                make_uint2(b0l, b1l);
        }
    }
}

// ---------------- launch 2: scatter --------------------------------------------
__global__ void k_scatter(const void* __restrict__ types, int E) {
    __shared__ int s_cnt[N_TYPES], s_base[N_TYPES];
    if (threadIdx.x < N_TYPES) s_cnt[threadIdx.x] = 0;
    __syncthreads();
    int e = blockIdx.x * blockDim.x + threadIdx.x;
    int t = 0, local = 0;
    int valid = (e < E);
    if (valid) {
        t = get_type(types, e, g_is64);
        local = atomicAdd(&s_cnt[t], 1);
    }
    __syncthreads();
    if (threadIdx.x < N_TYPES) {
        int off = 0;
        for (int u = 0; u < N_TYPES; u++) {
            if (u == threadIdx.x) break;
            off += g_counts[u];
        }
        s_base[threadIdx.x] = off + atomicAdd(&g_cursor[threadIdx.x], s_cnt[threadIdx.x]);
    }
    __syncthreads();
    if (valid) g_perm[s_base[t] + local] = e;
}

// ---------------- launch 3: persistent cp.async-pipelined grouped GEMM ---------
// smem (aligned): A planes 32KB | Xf32 double buffer 2x32KB | perm 2x512B
static constexpr int SM_X = 32768;
static constexpr int SM_PERM = 98304;
static constexpr int SMEM_DYN = 99328 + 1024;
static constexpr int NCTA = 296;

struct TileInfo {
    int type, row_start, m;
};

__device__ __forceinline__ TileInfo map_tile(int tl) {
    TileInfo ti;
    ti.type = -1;
    ti.row_start = 0;
    ti.m = 0;
    int acc_tiles = 0, off = 0;
#pragma unroll
    for (int t = 0; t < N_TYPES; t++) {
        int c = g_counts[t];
        int nt = (c + BM - 1) / BM;
        if (ti.type < 0 && tl < acc_tiles + nt) {
            ti.type = t;
            int lt = tl - acc_tiles;
            ti.row_start = off + lt * BM;
            ti.m = c - lt * BM;
            if (ti.m > BM) ti.m = BM;
        }
        acc_tiles += nt;
        off += c;
    }
    return ti;
}

__global__ void __launch_bounds__(256, 2) k_gemm_mma(const float* __restrict__ X,
                                                     const float* __restrict__ Bv,
                                                     float* __restrict__ out) {
    extern __shared__ char sm_raw[];
    uint32_t raw = smem_u32(sm_raw);
    uint32_t base = (raw + 1023) & ~1023u;
    char* pbase = sm_raw + (base - raw);
    uint32_t sA = base;
    uint32_t sX = base + SM_X;
    char* pX = pbase + SM_X;
    int* pperm = reinterpret_cast<int*>(pbase + SM_PERM);  // [2][128]

    int tid = threadIdx.x;
    int lane = tid & 31;
    int w = tid >> 5;

    int ntiles = 0;
#pragma unroll
    for (int t = 0; t < N_TYPES; t++) ntiles += (g_counts[t] + BM - 1) / BM;

    // lane maps
    int sub = lane >> 4;   // row within warp pair
    int q = lane & 15;     // 16B chunk within row
    int gc = q >> 1;
    int gsb = (q & 1) * 8;
    int wm = (w & 3) * 32;
    int wnq = (w >> 2);
    int wn = wnq * 32;
    int group = lane >> 2;
    int qc = lane & 3;
    int lrow[2];
#pragma unroll
    for (int mt = 0; mt < 2; mt++) lrow[mt] = wm + mt * 16 + (lane & 15);
    int cadd = lane >> 4;

    int tl = blockIdx.x;
    if (tl >= ntiles) return;

    // ---- prologue: perm(0) -> cp.async X(0) into buf 0 ----
    TileInfo cur = map_tile(tl);
    if (tid < BM) {
        int rr = (tid < cur.m) ? tid : (cur.m - 1);
        pperm[tid] = g_perm[cur.row_start + rr];
    }
    __syncthreads();
#pragma unroll
    for (int s = 0; s < 8; s++) {
        int r = s * 16 + w * 2 + sub;
        int e = pperm[r];
        cp_async16(sX + r * 256 + q * 16, X + (size_t)e * D + q * 4);
    }
    cp_commit();
    cp_wait0();
    __syncthreads();

    int buf = 0;

    for (; tl < ntiles; tl += NCTA) {
        // ---- convert Xf32[buf] -> bf16 planes in A ----
#pragma unroll
        for (int s = 0; s < 8; s++) {
            int r = s * 16 + w * 2 + sub;
            float4 v =
                *reinterpret_cast<const float4*>(pX + buf * 32768 + r * 256 + q * 16);
            uint32_t h0 = bf16x2(v.x, v.y);
            uint32_t h1 = bf16x2(v.z, v.w);
            uint32_t l0 = bf16x2(v.x - lo_of(h0), v.y - hi_of(h0));
            uint32_t l1 = bf16x2(v.z - lo_of(h1), v.w - hi_of(h1));
            uint32_t off = (uint32_t)r * 128 + (uint32_t)((gc ^ (r & 7)) << 4) + gsb;
            *reinterpret_cast<uint2*>(pbase + off) = make_uint2(h0, h1);
            *reinterpret_cast<uint2*>(pbase + 16384 + off) = make_uint2(l0, l1);
        }

        // ---- prefetch next tile's perm ----
        int tln = tl + NCTA;
        bool hasnext = (tln < ntiles);
        TileInfo nxt;
        if (hasnext) {
            nxt = map_tile(tln);
            if (tid < BM) {
                int rr = (tid < nxt.m) ? tid : (nxt.m - 1);
                pperm[(buf ^ 1) * BM + tid] = g_perm[nxt.row_start + rr];
            }
        }
        __syncthreads();  // A + perm_next visible; Xf32[buf^1] consumed long ago

        // ---- fire-and-forget gather of next tile into Xf32[buf^1] ----
        if (hasnext) {
            const int* pp = pperm + (buf ^ 1) * BM;
            uint32_t xb = sX + (buf ^ 1) * 32768;
#pragma unroll
            for (int s = 0; s < 8; s++) {
                int r = s * 16 + w * 2 + sub;
                int e = pp[r];
                cp_async16(xb + r * 256 + q * 16, X + (size_t)e * D + q * 4);
            }
        }
        cp_commit();

        // ---- MMA (A via ldmatrix from smem, B via L1-resident global) ----
        const uint2* gB = g_bfrag + (size_t)cur.type * 2048;

        float acc[2][4][4];
#pragma unroll
        for (int mt = 0; mt < 2; mt++)
#pragma unroll
            for (int nt = 0; nt < 4; nt++)
#pragma unroll
                for (int i = 0; i < 4; i++) acc[mt][nt][i] = 0.0f;

#pragma unroll
        for (int ks = 0; ks < 4; ks++) {
            uint32_t a[2][2][4];
#pragma unroll
            for (int mt = 0; mt < 2; mt++) {
                int c = ks * 2 + cadd;
                uint32_t off =
                    (uint32_t)lrow[mt] * 128 + (uint32_t)((c ^ (lrow[mt] & 7)) << 4);
                ldmx4(a[0][mt], sA + off);
                ldmx4(a[1][mt], sA + 16384 + off);
            }
            uint32_t b[2][4][2];
#pragma unroll
            for (int p = 0; p < 2; p++)
#pragma unroll
                for (int nt = 0; nt < 4; nt++) {
                    uint2 v = __ldg(&gB[((p * 4 + ks) * 8 + wnq * 4 + nt) * 32 + lane]);
                    b[p][nt][0] = v.x;
                    b[p][nt][1] = v.y;
                }
#pragma unroll
            for (int mt = 0; mt < 2; mt++)
#pragma unroll
                for (int nt = 0; nt < 4; nt++) {
                    mma_bf16(acc[mt][nt], a[0][mt], b[0][nt]);
                    mma_bf16(acc[mt][nt], a[0][mt], b[1][nt]);
                    mma_bf16(acc[mt][nt], a[1][mt], b[0][nt]);
                }
        }

        // ---- epilogue: bias + relu + scattered store ----
        float2 bias[4];
#pragma unroll
        for (int nt = 0; nt < 4; nt++) {
            bias[nt] = *reinterpret_cast<const float2*>(Bv + (size_t)cur.type * D +
                                                        wn + nt * 8 + qc * 2);
        }
        const int* ppc = pperm + buf * BM;
#pragma unroll
        for (int mt = 0; mt < 2; mt++) {
#pragma unroll
            for (int half = 0; half < 2; half++) {
                int r = wm + mt * 16 + group + half * 8;
                if (r < cur.m) {
                    int e = ppc[r];
                    float* orow = out + (size_t)e * D;
#pragma unroll
                    for (int nt = 0; nt < 4; nt++) {
                        float v0 = fmaxf(acc[mt][nt][half * 2 + 0] + bias[nt].x, 0.0f);
                        float v1 = fmaxf(acc[mt][nt][half * 2 + 1] + bias[nt].y, 0.0f);
                        *reinterpret_cast<float2*>(orow + wn + nt * 8 + qc * 2) =
                            make_float2(v0, v1);
                    }
                }
            }
        }

        cp_wait0();       // next tile's X landed
        __syncthreads();  // A fully consumed; Xf32[buf^1] ready for all
        cur = nxt;
        buf ^= 1;
    }
}

// ---------------- launch -------------------------------------------------------
extern "C" void kernel_launch(void* const* d_in, const int* in_sizes, int n_in,
                              void* d_out, int out_size) {
    const float* X = (const float*)d_in[0];
    const void* types = d_in[1];
    const float* W = (const float*)d_in[2];
    const float* Bv = (const float*)d_in[3];
    float* out = (float*)d_out;
    int E = in_sizes[0] / D;

    cudaFuncSetAttribute(k_gemm_mma, cudaFuncAttributeMaxDynamicSharedMemorySize,
                         SMEM_DYN);
    cudaFuncSetAttribute(k_gemm_mma,
                         cudaFuncAttributePreferredSharedMemoryCarveout, 100);

    k_init_detect<<<1, 256>>>((const int*)types, E);
    k_hist<<<512, 256>>>(types, W, E);
    k_scatter<<<(E + 255) / 256, 256>>>(types, E);

    k_gemm_mma<<<NCTA, 256, SMEM_DYN>>>(X, Bv, out);
}

// round 11
// speedup vs baseline: 1.7835x; 1.0630x over previous
#include <cuda_runtime.h>
#include <cuda_bf16.h>
#include <cstdint>

#define N_TYPES 8
#define D 64
#define BM 64
#define E_MAX 1048576

// ---------------- scratch ------------------------------------------------------
__device__ int g_counts[N_TYPES];
__device__ int g_cursor[N_TYPES];
__device__ int g_perm[E_MAX];
__device__ int g_is64;
// precomputed B fragments: [type][plane][ks][nt][lane] as uint2
__device__ uint2 g_bfrag[N_TYPES * 2 * 4 * 8 * 32];

// ---------------- helpers ------------------------------------------------------
__device__ __forceinline__ int get_type(const void* p, int i, int is64) {
    if (is64) return (int)((const long long*)p)[i];
    return ((const int*)p)[i];
}
__device__ __forceinline__ uint32_t bf16x2(float x0, float x1) {
    uint32_t r;
    asm("cvt.rn.bf16x2.f32 %0, %1, %2;" : "=r"(r) : "f"(x1), "f"(x0));
    return r;
}
__device__ __forceinline__ float lo_of(uint32_t w) { return __uint_as_float(w << 16); }
__device__ __forceinline__ float hi_of(uint32_t w) {
    return __uint_as_float(w & 0xffff0000u);
}
__device__ __forceinline__ void mma_bf16(float* c, const uint32_t* a,
                                         const uint32_t* b) {
    asm volatile(
        "mma.sync.aligned.m16n8k16.row.col.f32.bf16.bf16.f32 "
        "{%0,%1,%2,%3}, {%4,%5,%6,%7}, {%8,%9}, {%0,%1,%2,%3};"
        : "+f"(c[0]), "+f"(c[1]), "+f"(c[2]), "+f"(c[3])
        : "r"(a[0]), "r"(a[1]), "r"(a[2]), "r"(a[3]), "r"(b[0]), "r"(b[1]));
}
__device__ __forceinline__ void ldmx4(uint32_t* r, uint32_t addr) {
    asm volatile("ldmatrix.sync.aligned.m8n8.x4.shared.b16 {%0,%1,%2,%3}, [%4];"
                 : "=r"(r[0]), "=r"(r[1]), "=r"(r[2]), "=r"(r[3])
                 : "r"(addr));
}
__device__ __forceinline__ uint32_t smem_u32(const void* p) {
    uint32_t a;
    asm("{ .reg .u64 t; cvta.to.shared.u64 t, %1; cvt.u32.u64 %0, t; }"
        : "=r"(a) : "l"(p));
    return a;
}
__device__ __forceinline__ void cp_async16(uint32_t dst, const void* src) {
    asm volatile("cp.async.cg.shared.global [%0], [%1], 16;" ::"r"(dst), "l"(src)
                 : "memory");
}
__device__ __forceinline__ void cp_commit() {
    asm volatile("cp.async.commit_group;" ::: "memory");
}
__device__ __forceinline__ void cp_wait0() {
    asm volatile("cp.async.wait_group 0;" ::: "memory");
}

// ---------------- launch 0: init + dtype detect --------------------------------
__global__ void k_init_detect(const int* __restrict__ t32, int E) {
    __shared__ int any;
    if (threadIdx.x == 0) any = 0;
    if (threadIdx.x < N_TYPES) {
        g_counts[threadIdx.x] = 0;
        g_cursor[threadIdx.x] = 0;
    }
    __syncthreads();
    int stride = E / 2048;
    if (stride < 1) stride = 1;
    for (int i = threadIdx.x; i < 1024; i += blockDim.x) {
        long long idx = 2LL * i * stride + 1;
        if (idx < E && t32[idx] != 0) any = 1;
    }
    __syncthreads();
    if (threadIdx.x == 0) g_is64 = any ? 0 : 1;
}

// ---------------- launch 1: histogram + B-fragment precompute ------------------
__global__ void k_hist(const void* __restrict__ types, const float* __restrict__ W,
                       int E) {
    __shared__ int s[N_TYPES];
    if (threadIdx.x < N_TYPES) s[threadIdx.x] = 0;
    __syncthreads();
    int is64 = g_is64;
    for (int i = blockIdx.x * blockDim.x + threadIdx.x; i < E;
         i += gridDim.x * blockDim.x) {
        atomicAdd(&s[get_type(types, i, is64)], 1);
    }
    __syncthreads();
    if (threadIdx.x < N_TYPES) atomicAdd(&g_counts[threadIdx.x], s[threadIdx.x]);

    if (blockIdx.x < N_TYPES) {
        int t = blockIdx.x;
        const float* Wt = W + (size_t)t * D * D;
        for (int it = threadIdx.x; it < 4 * 8 * 32; it += blockDim.x) {
            int ks = it >> 8;
            int nt = (it >> 5) & 7;
            int lane = it & 31;
            int col = nt * 8 + (lane >> 2);
            int k0 = ks * 16 + 2 * (lane & 3);
            float w00 = Wt[k0 * D + col];
            float w01 = Wt[(k0 + 1) * D + col];
            float w10 = Wt[(k0 + 8) * D + col];
            float w11 = Wt[(k0 + 9) * D + col];
            uint32_t b0h = bf16x2(w00, w01);
            uint32_t b1h = bf16x2(w10, w11);
            uint32_t b0l = bf16x2(w00 - lo_of(b0h), w01 - hi_of(b0h));
            uint32_t b1l = bf16x2(w10 - lo_of(b1h), w11 - hi_of(b1h));
            g_bfrag[(((t * 2 + 0) * 4 + ks) * 8 + nt) * 32 + lane] =
                make_uint2(b0h, b1h);
            g_bfrag[(((t * 2 + 1) * 4 + ks) * 8 + nt) * 32 + lane] =
                make_uint2(b0l, b1l);
        }
    }
}

// ---------------- launch 2: scatter --------------------------------------------
__global__ void k_scatter(const void* __restrict__ types, int E) {
    __shared__ int s_cnt[N_TYPES], s_base[N_TYPES];
    if (threadIdx.x < N_TYPES) s_cnt[threadIdx.x] = 0;
    __syncthreads();
    int e = blockIdx.x * blockDim.x + threadIdx.x;
    int t = 0, local = 0;
    int valid = (e < E);
    if (valid) {
        t = get_type(types, e, g_is64);
        local = atomicAdd(&s_cnt[t], 1);
    }
    __syncthreads();
    if (threadIdx.x < N_TYPES) {
        int off = 0;
        for (int u = 0; u < N_TYPES; u++) {
            if (u == threadIdx.x) break;
            off += g_counts[u];
        }
        s_base[threadIdx.x] = off + atomicAdd(&g_cursor[threadIdx.x], s_cnt[threadIdx.x]);
    }
    __syncthreads();
    if (valid) g_perm[s_base[t] + local] = e;
}

// ---------------- launch 3: persistent small-CTA pipelined grouped GEMM --------
// 128 threads, BM=64, 4 warps (2m x 2n). 4 CTAs/SM (RF-exact).
// smem: A planes 16KB | Xf32 double buffer 2x16KB | perm 2x64 ints
static constexpr int SM_X = 16384;
static constexpr int SM_PERM = 49152;
static constexpr int SMEM_DYN = 49664 + 1024;
static constexpr int NCTA = 592;

struct TileInfo {
    int type, row_start, m;
};

__device__ __forceinline__ TileInfo map_tile(int tl) {
    TileInfo ti;
    ti.type = -1;
    ti.row_start = 0;
    ti.m = 0;
    int acc_tiles = 0, off = 0;
#pragma unroll
    for (int t = 0; t < N_TYPES; t++) {
        int c = g_counts[t];
        int nt = (c + BM - 1) / BM;
        if (ti.type < 0 && tl < acc_tiles + nt) {
            ti.type = t;
            int lt = tl - acc_tiles;
            ti.row_start = off + lt * BM;
            ti.m = c - lt * BM;
            if (ti.m > BM) ti.m = BM;
        }
        acc_tiles += nt;
        off += c;
    }
    return ti;
}

__global__ void __launch_bounds__(128, 4) k_gemm_mma(const float* __restrict__ X,
                                                     const float* __restrict__ Bv,
                                                     float* __restrict__ out) {
    extern __shared__ char sm_raw[];
    uint32_t raw = smem_u32(sm_raw);
    uint32_t base = (raw + 1023) & ~1023u;
    char* pbase = sm_raw + (base - raw);
    uint32_t sA = base;
    uint32_t sX = base + SM_X;
    char* pX = pbase + SM_X;
    int* pperm = reinterpret_cast<int*>(pbase + SM_PERM);  // [2][64]

    int tid = threadIdx.x;
    int lane = tid & 31;
    int w = tid >> 5;  // 0..3

    int ntiles = 0;
#pragma unroll
    for (int t = 0; t < N_TYPES; t++) ntiles += (g_counts[t] + BM - 1) / BM;

    // lane maps
    int sub = lane >> 4;   // row within warp pair
    int q = lane & 15;     // 16B chunk within row
    int gc = q >> 1;
    int gsb = (q & 1) * 8;
    int wm = (w & 1) * 32;   // warp m offset (2 warps in m)
    int wnq = (w >> 1) & 1;  // warp n quadrant (2 warps in n)
    int wn = wnq * 32;
    int group = lane >> 2;
    int qc = lane & 3;
    int lrow[2];
#pragma unroll
    for (int mt = 0; mt < 2; mt++) lrow[mt] = wm + mt * 16 + (lane & 15);
    int cadd = lane >> 4;

    int tl = blockIdx.x;
    if (tl >= ntiles) return;

    // ---- prologue: perm(0) -> cp.async X(0) into buf 0 ----
    TileInfo cur = map_tile(tl);
    if (tid < BM) {
        int rr = (tid < cur.m) ? tid : (cur.m - 1);
        pperm[tid] = g_perm[cur.row_start + rr];
    }
    __syncthreads();
#pragma unroll
    for (int s = 0; s < 8; s++) {
        int r = s * 8 + w * 2 + sub;
        int e = pperm[r];
        cp_async16(sX + r * 256 + q * 16, X + (size_t)e * D + q * 4);
    }
    cp_commit();
    cp_wait0();
    __syncthreads();

    int buf = 0;

    for (; tl < ntiles; tl += NCTA) {
        // ---- convert Xf32[buf] -> bf16 planes in A ----
#pragma unroll
        for (int s = 0; s < 8; s++) {
            int r = s * 8 + w * 2 + sub;
            float4 v =
                *reinterpret_cast<const float4*>(pX + buf * 16384 + r * 256 + q * 16);
            uint32_t h0 = bf16x2(v.x, v.y);
            uint32_t h1 = bf16x2(v.z, v.w);
            uint32_t l0 = bf16x2(v.x - lo_of(h0), v.y - hi_of(h0));
            uint32_t l1 = bf16x2(v.z - lo_of(h1), v.w - hi_of(h1));
            uint32_t off = (uint32_t)r * 128 + (uint32_t)((gc ^ (r & 7)) << 4) + gsb;
            *reinterpret_cast<uint2*>(pbase + off) = make_uint2(h0, h1);
            *reinterpret_cast<uint2*>(pbase + 8192 + off) = make_uint2(l0, l1);
        }

        // ---- prefetch next tile's perm ----
        int tln = tl + NCTA;
        bool hasnext = (tln < ntiles);
        TileInfo nxt;
        if (hasnext) {
            nxt = map_tile(tln);
            if (tid < BM) {
                int rr = (tid < nxt.m) ? tid : (nxt.m - 1);
                pperm[(buf ^ 1) * BM + tid] = g_perm[nxt.row_start + rr];
            }
        }
        __syncthreads();  // A + perm_next visible

        // ---- fire-and-forget gather of next tile into Xf32[buf^1] ----
        if (hasnext) {
            const int* pp = pperm + (buf ^ 1) * BM;
            uint32_t xb = sX + (buf ^ 1) * 16384;
#pragma unroll
            for (int s = 0; s < 8; s++) {
                int r = s * 8 + w * 2 + sub;
                int e = pp[r];
                cp_async16(xb + r * 256 + q * 16, X + (size_t)e * D + q * 4);
            }
        }
        cp_commit();

        // ---- MMA (A via ldmatrix from smem, B via L1-resident global) ----
        const uint2* gB = g_bfrag + (size_t)cur.type * 2048;

        float acc[2][4][4];
#pragma unroll
        for (int mt = 0; mt < 2; mt++)
#pragma unroll
            for (int nt = 0; nt < 4; nt++)
#pragma unroll
                for (int i = 0; i < 4; i++) acc[mt][nt][i] = 0.0f;

#pragma unroll
        for (int ks = 0; ks < 4; ks++) {
            uint32_t a[2][2][4];
#pragma unroll
            for (int mt = 0; mt < 2; mt++) {
                int c = ks * 2 + cadd;
                uint32_t off =
                    (uint32_t)lrow[mt] * 128 + (uint32_t)((c ^ (lrow[mt] & 7)) << 4);
                ldmx4(a[0][mt], sA + off);
                ldmx4(a[1][mt], sA + 8192 + off);
            }
            uint32_t b[2][4][2];
#pragma unroll
            for (int p = 0; p < 2; p++)
#pragma unroll
                for (int nt = 0; nt < 4; nt++) {
                    uint2 v = __ldg(&gB[((p * 4 + ks) * 8 + wnq * 4 + nt) * 32 + lane]);
                    b[p][nt][0] = v.x;
                    b[p][nt][1] = v.y;
                }
#pragma unroll
            for (int mt = 0; mt < 2; mt++)
#pragma unroll
                for (int nt = 0; nt < 4; nt++) {
                    mma_bf16(acc[mt][nt], a[0][mt], b[0][nt]);
                    mma_bf16(acc[mt][nt], a[0][mt], b[1][nt]);
                    mma_bf16(acc[mt][nt], a[1][mt], b[0][nt]);
                }
        }

        // ---- epilogue: bias + relu + scattered store ----
        float2 bias[4];
#pragma unroll
        for (int nt = 0; nt < 4; nt++) {
            bias[nt] = *reinterpret_cast<const float2*>(Bv + (size_t)cur.type * D +
                                                        wn + nt * 8 + qc * 2);
        }
        const int* ppc = pperm + buf * BM;
#pragma unroll
        for (int mt = 0; mt < 2; mt++) {
#pragma unroll
            for (int half = 0; half < 2; half++) {
                int r = wm + mt * 16 + group + half * 8;
                if (r < cur.m) {
                    int e = ppc[r];
                    float* orow = out + (size_t)e * D;
#pragma unroll
                    for (int nt = 0; nt < 4; nt++) {
                        float v0 = fmaxf(acc[mt][nt][half * 2 + 0] + bias[nt].x, 0.0f);
                        float v1 = fmaxf(acc[mt][nt][half * 2 + 1] + bias[nt].y, 0.0f);
                        *reinterpret_cast<float2*>(orow + wn + nt * 8 + qc * 2) =
                            make_float2(v0, v1);
                    }
                }
            }
        }

        cp_wait0();       // next tile's X landed
        __syncthreads();  // A fully consumed; Xf32[buf^1] ready
        cur = nxt;
        buf ^= 1;
    }
}

// ---------------- launch -------------------------------------------------------
extern "C" void kernel_launch(void* const* d_in, const int* in_sizes, int n_in,
                              void* d_out, int out_size) {
    const float* X = (const float*)d_in[0];
    const void* types = d_in[1];
    const float* W = (const float*)d_in[2];
    const float* Bv = (const float*)d_in[3];
    float* out = (float*)d_out;
    int E = in_sizes[0] / D;

    cudaFuncSetAttribute(k_gemm_mma, cudaFuncAttributeMaxDynamicSharedMemorySize,
                         SMEM_DYN);
    cudaFuncSetAttribute(k_gemm_mma,
                         cudaFuncAttributePreferredSharedMemoryCarveout, 100);

    k_init_detect<<<1, 256>>>((const int*)types, E);
    k_hist<<<512, 256>>>(types, W, E);
    k_scatter<<<(E + 255) / 256, 256>>>(types, E);

    k_gemm_mma<<<NCTA, 128, SMEM_DYN>>>(X, Bv, out);
}

// round 12
// speedup vs baseline: 1.8001x; 1.0093x over previous
#include <cuda_runtime.h>
#include <cuda_bf16.h>
#include <cstdint>

#define N_TYPES 8
#define D 64
#define BM 64
#define E_MAX 1048576

// ---------------- scratch ------------------------------------------------------
__device__ int g_counts[N_TYPES];
__device__ int g_cursor[N_TYPES];
__device__ int g_perm[E_MAX];
__device__ int g_is64;
// precomputed B fragments: [type][plane][ks][nt][lane] as uint2
__device__ uint2 g_bfrag[N_TYPES * 2 * 4 * 8 * 32];

// ---------------- helpers ------------------------------------------------------
__device__ __forceinline__ int get_type(const void* p, int i, int is64) {
    if (is64) return (int)((const long long*)p)[i];
    return ((const int*)p)[i];
}
__device__ __forceinline__ uint32_t bf16x2(float x0, float x1) {
    uint32_t r;
    asm("cvt.rn.bf16x2.f32 %0, %1, %2;" : "=r"(r) : "f"(x1), "f"(x0));
    return r;
}
__device__ __forceinline__ float lo_of(uint32_t w) { return __uint_as_float(w << 16); }
__device__ __forceinline__ float hi_of(uint32_t w) {
    return __uint_as_float(w & 0xffff0000u);
}
__device__ __forceinline__ void mma_bf16(float* c, const uint32_t* a,
                                         const uint32_t* b) {
    asm volatile(
        "mma.sync.aligned.m16n8k16.row.col.f32.bf16.bf16.f32 "
        "{%0,%1,%2,%3}, {%4,%5,%6,%7}, {%8,%9}, {%0,%1,%2,%3};"
        : "+f"(c[0]), "+f"(c[1]), "+f"(c[2]), "+f"(c[3])
        : "r"(a[0]), "r"(a[1]), "r"(a[2]), "r"(a[3]), "r"(b[0]), "r"(b[1]));
}
__device__ __forceinline__ void ldmx4(uint32_t* r, uint32_t addr) {
    asm volatile("ldmatrix.sync.aligned.m8n8.x4.shared.b16 {%0,%1,%2,%3}, [%4];"
                 : "=r"(r[0]), "=r"(r[1]), "=r"(r[2]), "=r"(r[3])
                 : "r"(addr));
}
__device__ __forceinline__ uint32_t smem_u32(const void* p) {
    uint32_t a;
    asm("{ .reg .u64 t; cvta.to.shared.u64 t, %1; cvt.u32.u64 %0, t; }"
        : "=r"(a) : "l"(p));
    return a;
}
__device__ __forceinline__ void cp_async16(uint32_t dst, const void* src) {
    asm volatile("cp.async.cg.shared.global [%0], [%1], 16;" ::"r"(dst), "l"(src)
                 : "memory");
}
__device__ __forceinline__ void cp_commit() {
    asm volatile("cp.async.commit_group;" ::: "memory");
}
__device__ __forceinline__ void cp_wait0() {
    asm volatile("cp.async.wait_group 0;" ::: "memory");
}

// ---------------- launch 0: init + dtype detect --------------------------------
__global__ void k_init_detect(const int* __restrict__ t32, int E) {
    __shared__ int any;
    if (threadIdx.x == 0) any = 0;
    if (threadIdx.x < N_TYPES) {
        g_counts[threadIdx.x] = 0;
        g_cursor[threadIdx.x] = 0;
    }
    __syncthreads();
    int stride = E / 2048;
    if (stride < 1) stride = 1;
    for (int i = threadIdx.x; i < 1024; i += blockDim.x) {
        long long idx = 2LL * i * stride + 1;
        if (idx < E && t32[idx] != 0) any = 1;
    }
    __syncthreads();
    if (threadIdx.x == 0) g_is64 = any ? 0 : 1;
}

// ---------------- launch 1: histogram + B-fragment precompute ------------------
__global__ void k_hist(const void* __restrict__ types, const float* __restrict__ W,
                       int E) {
    __shared__ int s[N_TYPES];
    if (threadIdx.x < N_TYPES) s[threadIdx.x] = 0;
    __syncthreads();
    int is64 = g_is64;
    for (int i = blockIdx.x * blockDim.x + threadIdx.x; i < E;
         i += gridDim.x * blockDim.x) {
        atomicAdd(&s[get_type(types, i, is64)], 1);
    }
    __syncthreads();
    if (threadIdx.x < N_TYPES) atomicAdd(&g_counts[threadIdx.x], s[threadIdx.x]);

    if (blockIdx.x < N_TYPES) {
        int t = blockIdx.x;
        const float* Wt = W + (size_t)t * D * D;
        for (int it = threadIdx.x; it < 4 * 8 * 32; it += blockDim.x) {
            int ks = it >> 8;
            int nt = (it >> 5) & 7;
            int lane = it & 31;
            int col = nt * 8 + (lane >> 2);
            int k0 = ks * 16 + 2 * (lane & 3);
            float w00 = Wt[k0 * D + col];
            float w01 = Wt[(k0 + 1) * D + col];
            float w10 = Wt[(k0 + 8) * D + col];
            float w11 = Wt[(k0 + 9) * D + col];
            uint32_t b0h = bf16x2(w00, w01);
            uint32_t b1h = bf16x2(w10, w11);
            uint32_t b0l = bf16x2(w00 - lo_of(b0h), w01 - hi_of(b0h));
            uint32_t b1l = bf16x2(w10 - lo_of(b1h), w11 - hi_of(b1h));
            g_bfrag[(((t * 2 + 0) * 4 + ks) * 8 + nt) * 32 + lane] =
                make_uint2(b0h, b1h);
            g_bfrag[(((t * 2 + 1) * 4 + ks) * 8 + nt) * 32 + lane] =
                make_uint2(b0l, b1l);
        }
    }
}

// ---------------- launch 2: scatter --------------------------------------------
__global__ void k_scatter(const void* __restrict__ types, int E) {
    __shared__ int s_cnt[N_TYPES], s_base[N_TYPES];
    if (threadIdx.x < N_TYPES) s_cnt[threadIdx.x] = 0;
    __syncthreads();
    int e = blockIdx.x * blockDim.x + threadIdx.x;
    int t = 0, local = 0;
    int valid = (e < E);
    if (valid) {
        t = get_type(types, e, g_is64);
        local = atomicAdd(&s_cnt[t], 1);
    }
    __syncthreads();
    if (threadIdx.x < N_TYPES) {
        int off = 0;
        for (int u = 0; u < N_TYPES; u++) {
            if (u == threadIdx.x) break;
            off += g_counts[u];
        }
        s_base[threadIdx.x] = off + atomicAdd(&g_cursor[threadIdx.x], s_cnt[threadIdx.x]);
    }
    __syncthreads();
    if (valid) g_perm[s_base[t] + local] = e;
}

// ---------------- launch 3: persistent single-X-buffer pipelined GEMM ----------
// 128 threads, BM=64, 4 warps (2m x 2n). 5 CTAs/SM target.
// smem: A planes 16KB | Xf32 single buffer 16KB | perm 2x64 ints
static constexpr int SM_X = 16384;
static constexpr int SM_PERM = 32768;
static constexpr int SMEM_DYN = 33280 + 1024;
static constexpr int NCTA = 740;

struct TileInfo {
    int type, row_start, m;
};

__device__ __forceinline__ TileInfo map_tile(int tl) {
    TileInfo ti;
    ti.type = -1;
    ti.row_start = 0;
    ti.m = 0;
    int acc_tiles = 0, off = 0;
#pragma unroll
    for (int t = 0; t < N_TYPES; t++) {
        int c = g_counts[t];
        int nt = (c + BM - 1) / BM;
        if (ti.type < 0 && tl < acc_tiles + nt) {
            ti.type = t;
            int lt = tl - acc_tiles;
            ti.row_start = off + lt * BM;
            ti.m = c - lt * BM;
            if (ti.m > BM) ti.m = BM;
        }
        acc_tiles += nt;
        off += c;
    }
    return ti;
}

__global__ void __launch_bounds__(128, 5) k_gemm_mma(const float* __restrict__ X,
                                                     const float* __restrict__ Bv,
                                                     float* __restrict__ out) {
    extern __shared__ char sm_raw[];
    uint32_t raw = smem_u32(sm_raw);
    uint32_t base = (raw + 1023) & ~1023u;
    char* pbase = sm_raw + (base - raw);
    uint32_t sA = base;
    uint32_t sX = base + SM_X;
    char* pX = pbase + SM_X;
    int* pperm = reinterpret_cast<int*>(pbase + SM_PERM);  // [2][64]

    int tid = threadIdx.x;
    int lane = tid & 31;
    int w = tid >> 5;  // 0..3

    int ntiles = 0;
#pragma unroll
    for (int t = 0; t < N_TYPES; t++) ntiles += (g_counts[t] + BM - 1) / BM;

    // lane maps
    int sub = lane >> 4;   // row within warp pair
    int q = lane & 15;     // 16B chunk within row
    int gc = q >> 1;
    int gsb = (q & 1) * 8;
    int wm = (w & 1) * 32;   // warp m offset
    int wnq = (w >> 1) & 1;  // warp n quadrant
    int wn = wnq * 32;
    int group = lane >> 2;
    int qc = lane & 3;
    int lrow[2];
#pragma unroll
    for (int mt = 0; mt < 2; mt++) lrow[mt] = wm + mt * 16 + (lane & 15);
    int cadd = lane >> 4;

    int tl = blockIdx.x;
    if (tl >= ntiles) return;

    // ---- prologue: perm(0) -> cp.async X(0) ----
    TileInfo cur = map_tile(tl);
    if (tid < BM) {
        int rr = (tid < cur.m) ? tid : (cur.m - 1);
        pperm[tid] = g_perm[cur.row_start + rr];
    }
    __syncthreads();
#pragma unroll
    for (int s = 0; s < 8; s++) {
        int r = s * 8 + w * 2 + sub;
        int e = pperm[r];
        cp_async16(sX + r * 256 + q * 16, X + (size_t)e * D + q * 4);
    }
    cp_commit();
    cp_wait0();
    __syncthreads();

    int buf = 0;  // perm buffer parity only

    for (; tl < ntiles; tl += NCTA) {
        // ---- convert Xf32 -> bf16 planes in A (last reads of X) ----
#pragma unroll
        for (int s = 0; s < 8; s++) {
            int r = s * 8 + w * 2 + sub;
            float4 v = *reinterpret_cast<const float4*>(pX + r * 256 + q * 16);
            uint32_t h0 = bf16x2(v.x, v.y);
            uint32_t h1 = bf16x2(v.z, v.w);
            uint32_t l0 = bf16x2(v.x - lo_of(h0), v.y - hi_of(h0));
            uint32_t l1 = bf16x2(v.z - lo_of(h1), v.w - hi_of(h1));
            uint32_t off = (uint32_t)r * 128 + (uint32_t)((gc ^ (r & 7)) << 4) + gsb;
            *reinterpret_cast<uint2*>(pbase + off) = make_uint2(h0, h1);
            *reinterpret_cast<uint2*>(pbase + 8192 + off) = make_uint2(l0, l1);
        }

        // ---- prefetch next tile's perm ----
        int tln = tl + NCTA;
        bool hasnext = (tln < ntiles);
        TileInfo nxt;
        if (hasnext) {
            nxt = map_tile(tln);
            if (tid < BM) {
                int rr = (tid < nxt.m) ? tid : (nxt.m - 1);
                pperm[(buf ^ 1) * BM + tid] = g_perm[nxt.row_start + rr];
            }
        }
        __syncthreads();  // A visible; X fully consumed by ALL threads

        // ---- fire-and-forget gather of next tile into the SAME X buffer ----
        if (hasnext) {
            const int* pp = pperm + (buf ^ 1) * BM;
#pragma unroll
            for (int s = 0; s < 8; s++) {
                int r = s * 8 + w * 2 + sub;
                int e = pp[r];
                cp_async16(sX + r * 256 + q * 16, X + (size_t)e * D + q * 4);
            }
        }
        cp_commit();

        // ---- MMA (A via ldmatrix, B via L1-resident global; B planes serial) ----
        const uint2* gB = g_bfrag + (size_t)cur.type * 2048;

        float acc[2][4][4];
#pragma unroll
        for (int mt = 0; mt < 2; mt++)
#pragma unroll
            for (int nt = 0; nt < 4; nt++)
#pragma unroll
                for (int i = 0; i < 4; i++) acc[mt][nt][i] = 0.0f;

#pragma unroll
        for (int ks = 0; ks < 4; ks++) {
            uint32_t a[2][2][4];
#pragma unroll
            for (int mt = 0; mt < 2; mt++) {
                int c = ks * 2 + cadd;
                uint32_t off =
                    (uint32_t)lrow[mt] * 128 + (uint32_t)((c ^ (lrow[mt] & 7)) << 4);
                ldmx4(a[0][mt], sA + off);
                ldmx4(a[1][mt], sA + 8192 + off);
            }
            // plane 0 of B: hi*b0 and lo*b0
            {
                uint32_t b[4][2];
#pragma unroll
                for (int nt = 0; nt < 4; nt++) {
                    uint2 v = __ldg(&gB[((0 * 4 + ks) * 8 + wnq * 4 + nt) * 32 + lane]);
                    b[nt][0] = v.x;
                    b[nt][1] = v.y;
                }
#pragma unroll
                for (int mt = 0; mt < 2; mt++)
#pragma unroll
                    for (int nt = 0; nt < 4; nt++) {
                        mma_bf16(acc[mt][nt], a[0][mt], b[nt]);
                        mma_bf16(acc[mt][nt], a[1][mt], b[nt]);
                    }
            }
            // plane 1 of B: hi*b1
            {
                uint32_t b[4][2];
#pragma unroll
                for (int nt = 0; nt < 4; nt++) {
                    uint2 v = __ldg(&gB[((1 * 4 + ks) * 8 + wnq * 4 + nt) * 32 + lane]);
                    b[nt][0] = v.x;
                    b[nt][1] = v.y;
                }
#pragma unroll
                for (int mt = 0; mt < 2; mt++)
#pragma unroll
                    for (int nt = 0; nt < 4; nt++) {
                        mma_bf16(acc[mt][nt], a[0][mt], b[nt]);
                    }
            }
        }

        // ---- epilogue: bias + relu + scattered store ----
        float2 bias[4];
#pragma unroll
        for (int nt = 0; nt < 4; nt++) {
            bias[nt] = *reinterpret_cast<const float2*>(Bv + (size_t)cur.type * D +
                                                        wn + nt * 8 + qc * 2);
        }
        const int* ppc = pperm + buf * BM;
#pragma unroll
        for (int mt = 0; mt < 2; mt++) {
#pragma unroll
            for (int half = 0; half < 2; half++) {
                int r = wm + mt * 16 + group + half * 8;
                if (r < cur.m) {
                    int e = ppc[r];
                    float* orow = out + (size_t)e * D;
#pragma unroll
                    for (int nt = 0; nt < 4; nt++) {
                        float v0 = fmaxf(acc[mt][nt][half * 2 + 0] + bias[nt].x, 0.0f);
                        float v1 = fmaxf(acc[mt][nt][half * 2 + 1] + bias[nt].y, 0.0f);
                        *reinterpret_cast<float2*>(orow + wn + nt * 8 + qc * 2) =
                            make_float2(v0, v1);
                    }
                }
            }
        }

        cp_wait0();       // next tile's X landed
        __syncthreads();  // A consumed; X ready for convert
        cur = nxt;
        buf ^= 1;
    }
}

// ---------------- launch -------------------------------------------------------
extern "C" void kernel_launch(void* const* d_in, const int* in_sizes, int n_in,
                              void* d_out, int out_size) {
    const float* X = (const float*)d_in[0];
    const void* types = d_in[1];
    const float* W = (const float*)d_in[2];
    const float* Bv = (const float*)d_in[3];
    float* out = (float*)d_out;
    int E = in_sizes[0] / D;

    cudaFuncSetAttribute(k_gemm_mma, cudaFuncAttributeMaxDynamicSharedMemorySize,
                         SMEM_DYN);
    cudaFuncSetAttribute(k_gemm_mma,
                         cudaFuncAttributePreferredSharedMemoryCarveout, 100);

    k_init_detect<<<1, 256>>>((const int*)types, E);
    k_hist<<<512, 256>>>(types, W, E);
    k_scatter<<<(E + 255) / 256, 256>>>(types, E);

    k_gemm_mma<<<NCTA, 128, SMEM_DYN>>>(X, Bv, out);
}

// round 13
// speedup vs baseline: 1.8603x; 1.0335x over previous
#include <cuda_runtime.h>
#include <cuda_bf16.h>
#include <cstdint>

#define N_TYPES 8
#define D 64
#define BM 64
#define E_MAX 1048576

// ---------------- scratch ------------------------------------------------------
__device__ int g_cursor[N_TYPES];
__device__ int g_perm[N_TYPES * E_MAX];  // fixed region per type
__device__ int g_is64;
// precomputed B fragments: [type][plane][ks][nt][lane] as uint2
__device__ uint2 g_bfrag[N_TYPES * 2 * 4 * 8 * 32];

// ---------------- helpers ------------------------------------------------------
__device__ __forceinline__ int get_type(const void* p, int i, int is64) {
    if (is64) return (int)((const long long*)p)[i];
    return ((const int*)p)[i];
}
__device__ __forceinline__ uint32_t bf16x2(float x0, float x1) {
    uint32_t r;
    asm("cvt.rn.bf16x2.f32 %0, %1, %2;" : "=r"(r) : "f"(x1), "f"(x0));
    return r;
}
__device__ __forceinline__ float lo_of(uint32_t w) { return __uint_as_float(w << 16); }
__device__ __forceinline__ float hi_of(uint32_t w) {
    return __uint_as_float(w & 0xffff0000u);
}
__device__ __forceinline__ void mma_bf16(float* c, const uint32_t* a,
                                         const uint32_t* b) {
    asm volatile(
        "mma.sync.aligned.m16n8k16.row.col.f32.bf16.bf16.f32 "
        "{%0,%1,%2,%3}, {%4,%5,%6,%7}, {%8,%9}, {%0,%1,%2,%3};"
        : "+f"(c[0]), "+f"(c[1]), "+f"(c[2]), "+f"(c[3])
        : "r"(a[0]), "r"(a[1]), "r"(a[2]), "r"(a[3]), "r"(b[0]), "r"(b[1]));
}
__device__ __forceinline__ void ldmx4(uint32_t* r, uint32_t addr) {
    asm volatile("ldmatrix.sync.aligned.m8n8.x4.shared.b16 {%0,%1,%2,%3}, [%4];"
                 : "=r"(r[0]), "=r"(r[1]), "=r"(r[2]), "=r"(r[3])
                 : "r"(addr));
}
__device__ __forceinline__ uint32_t smem_u32(const void* p) {
    uint32_t a;
    asm("{ .reg .u64 t; cvta.to.shared.u64 t, %1; cvt.u32.u64 %0, t; }"
        : "=r"(a) : "l"(p));
    return a;
}
__device__ __forceinline__ void cp_async16(uint32_t dst, const void* src) {
    asm volatile("cp.async.cg.shared.global [%0], [%1], 16;" ::"r"(dst), "l"(src)
                 : "memory");
}
__device__ __forceinline__ void cp_commit() {
    asm volatile("cp.async.commit_group;" ::: "memory");
}
__device__ __forceinline__ void cp_wait0() {
    asm volatile("cp.async.wait_group 0;" ::: "memory");
}

// ---------------- launch 0: init + dtype detect --------------------------------
__global__ void k_init_detect(const int* __restrict__ t32, int E) {
    __shared__ int any;
    if (threadIdx.x == 0) any = 0;
    if (threadIdx.x < N_TYPES) g_cursor[threadIdx.x] = 0;
    __syncthreads();
    int stride = E / 2048;
    if (stride < 1) stride = 1;
    for (int i = threadIdx.x; i < 1024; i += blockDim.x) {
        long long idx = 2LL * i * stride + 1;
        if (idx < E && t32[idx] != 0) any = 1;
    }
    __syncthreads();
    if (threadIdx.x == 0) g_is64 = any ? 0 : 1;
}

// ---------------- launch 1: scatter into fixed regions + B-frag build ----------
__global__ void k_scatter(const void* __restrict__ types,
                          const float* __restrict__ W, int E) {
    __shared__ int s_cnt[N_TYPES], s_base[N_TYPES];
    if (threadIdx.x < N_TYPES) s_cnt[threadIdx.x] = 0;
    __syncthreads();
    int e = blockIdx.x * blockDim.x + threadIdx.x;
    int t = 0, local = 0;
    int valid = (e < E);
    if (valid) {
        t = get_type(types, e, g_is64);
        local = atomicAdd(&s_cnt[t], 1);
    }
    __syncthreads();
    if (threadIdx.x < N_TYPES) {
        s_base[threadIdx.x] = threadIdx.x * E_MAX +
                              atomicAdd(&g_cursor[threadIdx.x], s_cnt[threadIdx.x]);
    }
    __syncthreads();
    if (valid) g_perm[s_base[t] + local] = e;

    // blocks 0..7: build B fragments for type = blockIdx.x
    if (blockIdx.x < N_TYPES) {
        int ty = blockIdx.x;
        const float* Wt = W + (size_t)ty * D * D;
        for (int it = threadIdx.x; it < 4 * 8 * 32; it += blockDim.x) {
            int ks = it >> 8;
            int nt = (it >> 5) & 7;
            int lane = it & 31;
            int col = nt * 8 + (lane >> 2);
            int k0 = ks * 16 + 2 * (lane & 3);
            float w00 = Wt[k0 * D + col];
            float w01 = Wt[(k0 + 1) * D + col];
            float w10 = Wt[(k0 + 8) * D + col];
            float w11 = Wt[(k0 + 9) * D + col];
            uint32_t b0h = bf16x2(w00, w01);
            uint32_t b1h = bf16x2(w10, w11);
            uint32_t b0l = bf16x2(w00 - lo_of(b0h), w01 - hi_of(b0h));
            uint32_t b1l = bf16x2(w10 - lo_of(b1h), w11 - hi_of(b1h));
            g_bfrag[(((ty * 2 + 0) * 4 + ks) * 8 + nt) * 32 + lane] =
                make_uint2(b0h, b1h);
            g_bfrag[(((ty * 2 + 1) * 4 + ks) * 8 + nt) * 32 + lane] =
                make_uint2(b0l, b1l);
        }
    }
}

// ---------------- launch 2: persistent pipelined GEMM, 6 CTAs/SM ---------------
// 128 threads, BM=64, 4 warps (2m x 2n).
// smem: A planes 16KB | Xf32 single buffer 16KB | perm 2x64 ints
static constexpr int SM_X = 16384;
static constexpr int SM_PERM = 32768;
static constexpr int SMEM_DYN = 33280 + 1024;
static constexpr int NCTA = 888;

struct TileInfo {
    int type, row_start, m;
};

__device__ __forceinline__ TileInfo map_tile(int tl) {
    TileInfo ti;
    ti.type = -1;
    ti.row_start = 0;
    ti.m = 0;
    int acc_tiles = 0;
#pragma unroll
    for (int t = 0; t < N_TYPES; t++) {
        int c = g_cursor[t];
        int nt = (c + BM - 1) / BM;
        if (ti.type < 0 && tl < acc_tiles + nt) {
            ti.type = t;
            int lt = tl - acc_tiles;
            ti.row_start = t * E_MAX + lt * BM;
            ti.m = c - lt * BM;
            if (ti.m > BM) ti.m = BM;
        }
        acc_tiles += nt;
    }
    return ti;
}

__global__ void __launch_bounds__(128, 6) k_gemm_mma(const float* __restrict__ X,
                                                     const float* __restrict__ Bv,
                                                     float* __restrict__ out) {
    extern __shared__ char sm_raw[];
    uint32_t raw = smem_u32(sm_raw);
    uint32_t base = (raw + 1023) & ~1023u;
    char* pbase = sm_raw + (base - raw);
    uint32_t sA = base;
    uint32_t sX = base + SM_X;
    char* pX = pbase + SM_X;
    int* pperm = reinterpret_cast<int*>(pbase + SM_PERM);  // [2][64]

    int tid = threadIdx.x;
    int lane = tid & 31;
    int w = tid >> 5;  // 0..3

    int ntiles = 0;
#pragma unroll
    for (int t = 0; t < N_TYPES; t++) ntiles += (g_cursor[t] + BM - 1) / BM;

    // lane maps
    int sub = lane >> 4;
    int q = lane & 15;
    int gc = q >> 1;
    int gsb = (q & 1) * 8;
    int wm = (w & 1) * 32;
    int wnq = (w >> 1) & 1;
    int wn = wnq * 32;
    int group = lane >> 2;
    int qc = lane & 3;
    int lrow[2];
#pragma unroll
    for (int mt = 0; mt < 2; mt++) lrow[mt] = wm + mt * 16 + (lane & 15);
    int cadd = lane >> 4;

    int tl = blockIdx.x;
    if (tl >= ntiles) return;

    // ---- prologue ----
    TileInfo cur = map_tile(tl);
    if (tid < BM) {
        int rr = (tid < cur.m) ? tid : (cur.m - 1);
        pperm[tid] = g_perm[cur.row_start + rr];
    }
    __syncthreads();
#pragma unroll
    for (int s = 0; s < 8; s++) {
        int r = s * 8 + w * 2 + sub;
        int e = pperm[r];
        cp_async16(sX + r * 256 + q * 16, X + (size_t)e * D + q * 4);
    }
    cp_commit();
    cp_wait0();
    __syncthreads();

    int buf = 0;
    int btype = -1;
    float2 bias[4];

    for (; tl < ntiles; tl += NCTA) {
        // ---- bias cache (reload on type change only) ----
        if (cur.type != btype) {
            btype = cur.type;
#pragma unroll
            for (int nt = 0; nt < 4; nt++) {
                bias[nt] = *reinterpret_cast<const float2*>(
                    Bv + (size_t)btype * D + wn + nt * 8 + qc * 2);
            }
        }

        // ---- convert Xf32 -> bf16 planes in A ----
#pragma unroll
        for (int s = 0; s < 8; s++) {
            int r = s * 8 + w * 2 + sub;
            float4 v = *reinterpret_cast<const float4*>(pX + r * 256 + q * 16);
            uint32_t h0 = bf16x2(v.x, v.y);
            uint32_t h1 = bf16x2(v.z, v.w);
            uint32_t l0 = bf16x2(v.x - lo_of(h0), v.y - hi_of(h0));
            uint32_t l1 = bf16x2(v.z - lo_of(h1), v.w - hi_of(h1));
            uint32_t off = (uint32_t)r * 128 + (uint32_t)((gc ^ (r & 7)) << 4) + gsb;
            *reinterpret_cast<uint2*>(pbase + off) = make_uint2(h0, h1);
            *reinterpret_cast<uint2*>(pbase + 8192 + off) = make_uint2(l0, l1);
        }

        // ---- prefetch next tile's perm ----
        int tln = tl + NCTA;
        bool hasnext = (tln < ntiles);
        TileInfo nxt;
        if (hasnext) {
            nxt = map_tile(tln);
            if (tid < BM) {
                int rr = (tid < nxt.m) ? tid : (nxt.m - 1);
                pperm[(buf ^ 1) * BM + tid] = g_perm[nxt.row_start + rr];
            }
        }
        __syncthreads();  // A visible; X fully consumed

        // ---- gather next tile into the same X buffer ----
        if (hasnext) {
            const int* pp = pperm + (buf ^ 1) * BM;
#pragma unroll
            for (int s = 0; s < 8; s++) {
                int r = s * 8 + w * 2 + sub;
                int e = pp[r];
                cp_async16(sX + r * 256 + q * 16, X + (size_t)e * D + q * 4);
            }
        }
        cp_commit();

        // ---- MMA: per-nt serialized B (minimal live b regs) ----
        const uint2* gB = g_bfrag + (size_t)cur.type * 2048;

        float acc[2][4][4];
#pragma unroll
        for (int mt = 0; mt < 2; mt++)
#pragma unroll
            for (int nt = 0; nt < 4; nt++)
#pragma unroll
                for (int i = 0; i < 4; i++) acc[mt][nt][i] = 0.0f;

#pragma unroll
        for (int ks = 0; ks < 4; ks++) {
            uint32_t a[2][2][4];  // [plane][mt][reg]
#pragma unroll
            for (int mt = 0; mt < 2; mt++) {
                int c = ks * 2 + cadd;
                uint32_t off =
                    (uint32_t)lrow[mt] * 128 + (uint32_t)((c ^ (lrow[mt] & 7)) << 4);
                ldmx4(a[0][mt], sA + off);
                ldmx4(a[1][mt], sA + 8192 + off);
            }
#pragma unroll
            for (int nt = 0; nt < 4; nt++) {
                uint32_t b[2];
                {
                    uint2 v = __ldg(&gB[((0 * 4 + ks) * 8 + wnq * 4 + nt) * 32 + lane]);
                    b[0] = v.x;
                    b[1] = v.y;
                }
                mma_bf16(acc[0][nt], a[0][0], b);  // hi_a * hi_b
                mma_bf16(acc[1][nt], a[0][1], b);
                mma_bf16(acc[0][nt], a[1][0], b);  // lo_a * hi_b
                mma_bf16(acc[1][nt], a[1][1], b);
                {
                    uint2 v = __ldg(&gB[((1 * 4 + ks) * 8 + wnq * 4 + nt) * 32 + lane]);
                    b[0] = v.x;
                    b[1] = v.y;
                }
                mma_bf16(acc[0][nt], a[0][0], b);  // hi_a * lo_b
                mma_bf16(acc[1][nt], a[0][1], b);
            }
        }

        // ---- epilogue: bias + relu + scattered store ----
        const int* ppc = pperm + buf * BM;
#pragma unroll
        for (int mt = 0; mt < 2; mt++) {
#pragma unroll
            for (int half = 0; half < 2; half++) {
                int r = wm + mt * 16 + group + half * 8;
                if (r < cur.m) {
                    int e = ppc[r];
                    float* orow = out + (size_t)e * D;
#pragma unroll
                    for (int nt = 0; nt < 4; nt++) {
                        float v0 = fmaxf(acc[mt][nt][half * 2 + 0] + bias[nt].x, 0.0f);
                        float v1 = fmaxf(acc[mt][nt][half * 2 + 1] + bias[nt].y, 0.0f);
                        *reinterpret_cast<float2*>(orow + wn + nt * 8 + qc * 2) =
                            make_float2(v0, v1);
                    }
                }
            }
        }

        cp_wait0();
        __syncthreads();
        cur = nxt;
        buf ^= 1;
    }
}

// ---------------- launch -------------------------------------------------------
extern "C" void kernel_launch(void* const* d_in, const int* in_sizes, int n_in,
                              void* d_out, int out_size) {
    const float* X = (const float*)d_in[0];
    const void* types = d_in[1];
    const float* W = (const float*)d_in[2];
    const float* Bv = (const float*)d_in[3];
    float* out = (float*)d_out;
    int E = in_sizes[0] / D;

    cudaFuncSetAttribute(k_gemm_mma, cudaFuncAttributeMaxDynamicSharedMemorySize,
                         SMEM_DYN);
    cudaFuncSetAttribute(k_gemm_mma,
                         cudaFuncAttributePreferredSharedMemoryCarveout, 100);

    k_init_detect<<<1, 256>>>((const int*)types, E);
    k_scatter<<<(E + 255) / 256, 256>>>(types, W, E);

    k_gemm_mma<<<NCTA, 128, SMEM_DYN>>>(X, Bv, out);
}